// round 10
// baseline (speedup 1.0000x reference)
#include <cuda_runtime.h>
#include <cuda_bf16.h>
#include <mma.h>
#include <math.h>

using namespace nvcuda;

// Problem constants (shapes fixed by the dataset).
#define NN      50000
#define EEDGES  800000
#define IN_DIM  128
#define H1N     4
#define C1N     64
#define D1      (H1N * C1N)          // 256
#define D2      64
#define EPS_BN  1e-5f
#define NEG_SLOPE 0.2f
#define NEG_BIG  (-1e30f)

// -------------------- scratch (static __device__, no allocs) ----------------
__device__ float    g_h1  [NN * D1];       // x@W1 (layer-1 lin output)
__device__ float    g_o1  [NN * D1];       // GAT1 aggregation output (pre-BN)
__device__ float    g_as1 [NN * H1N];
__device__ float    g_ad1 [NN * H1N];
__device__ float    g_h2  [NN * D2];       // layer-2 lin output
__device__ float    g_o2  [NN * D2];       // GAT2 aggregation output (pre-BN)
__device__ float    g_as2 [NN];
__device__ float    g_ad2 [NN];
__device__ float    g_proj[NN * IN_DIM];
__device__ int      g_deg [NN];
__device__ int      g_rowptr[NN + 1];
__device__ int      g_cursor[NN];
__device__ int      g_srcs[EEDGES];
__device__ double   g_sum [256];
__device__ double   g_sq  [256];
__device__ float    g_mean[256];           // BN1 stats
__device__ float    g_rstd[256];
__device__ double   g_sum2[64];
__device__ double   g_sq2 [64];
__device__ float    g_mean2[64];           // BN2 stats
__device__ float    g_rstd2[64];

__device__ __forceinline__ float lrelu(float v) {
    return v > 0.f ? v : NEG_SLOPE * v;
}
__device__ __forceinline__ float bn_elu(float v, float mu, float rs, float ga, float bb) {
    float t = (v - mu) * rs * ga + bb;
    return t > 0.f ? t : __expf(t) - 1.f;
}

// ------------- GEMM (TF32 tensor cores): C[M,Nc] = A[M,K] @ B[K,Nc] ---------
// BM=128, BN=64, BK=16. 256 threads = 8 warps in 4x2; each warp 32x32 output
// via 2x2 wmma m16n16k8 accumulators. A,B staged in smem as tf32.
// FUSE_BN: apply per-K-channel BN+ELU to A elements while staging (BN-then-GEMM).
#define GBM 128
#define GBN 64
#define ALD 20      // A smem leading dim (mult of 4)
#define BLD 68      // B smem leading dim (mult of 4)
template<bool FUSE_BN>
__global__ __launch_bounds__(256) void gemm_tf32_kernel(
    const float* __restrict__ A, const float* __restrict__ B,
    float* __restrict__ C, int M, int Nc, int K,
    const float* __restrict__ bn_mean, const float* __restrict__ bn_rstd,
    const float* __restrict__ bn_g,    const float* __restrict__ bn_be)
{
    __shared__ float As[GBM][ALD];   // 128x16 tile (tf32 values)
    __shared__ float Bs[16][BLD];    // 16x64 tile
    int tid = threadIdx.x;
    int wid  = tid >> 5;
    int wrow = wid >> 1;             // 0..3 -> 32-row strip
    int wcol = wid & 1;              // 0..1 -> 32-col strip
    int row0 = blockIdx.y * GBM, col0 = blockIdx.x * GBN;

    wmma::fragment<wmma::accumulator, 16, 16, 8, float> acc[2][2];
    #pragma unroll
    for (int i = 0; i < 2; i++)
        #pragma unroll
        for (int j = 0; j < 2; j++) wmma::fill_fragment(acc[i][j], 0.f);

    for (int k0 = 0; k0 < K; k0 += 16) {
        {   // A tile: 128 rows x 16 k. Each thread: one row, 8 k (2 float4).
            int r  = tid >> 1;
            int c8 = (tid & 1) * 8;
            float4 v0 = make_float4(0, 0, 0, 0), v1 = v0;
            if (row0 + r < M) {
                const float* ap = A + (size_t)(row0 + r) * K + k0 + c8;
                v0 = *(const float4*)ap;
                v1 = *(const float4*)(ap + 4);
            }
            float av[8] = {v0.x, v0.y, v0.z, v0.w, v1.x, v1.y, v1.z, v1.w};
            if (FUSE_BN) {
                #pragma unroll
                for (int j = 0; j < 8; j++) {
                    int c = k0 + c8 + j;
                    av[j] = bn_elu(av[j], bn_mean[c], bn_rstd[c], bn_g[c], bn_be[c]);
                }
            }
            #pragma unroll
            for (int j = 0; j < 8; j++)
                As[r][c8 + j] = wmma::__float_to_tf32(av[j]);
        }
        {   // B tile: 16 k x 64 cols. Each thread one float4.
            int r  = tid >> 4;
            int c4 = (tid & 15) * 4;
            float4 v = *(const float4*)(B + (size_t)(k0 + r) * Nc + col0 + c4);
            Bs[r][c4 + 0] = wmma::__float_to_tf32(v.x);
            Bs[r][c4 + 1] = wmma::__float_to_tf32(v.y);
            Bs[r][c4 + 2] = wmma::__float_to_tf32(v.z);
            Bs[r][c4 + 3] = wmma::__float_to_tf32(v.w);
        }
        __syncthreads();
        #pragma unroll
        for (int kk = 0; kk < 16; kk += 8) {
            wmma::fragment<wmma::matrix_a, 16, 16, 8, wmma::precision::tf32, wmma::row_major> af[2];
            wmma::fragment<wmma::matrix_b, 16, 16, 8, wmma::precision::tf32, wmma::row_major> bf[2];
            wmma::load_matrix_sync(af[0], &As[wrow * 32     ][kk], ALD);
            wmma::load_matrix_sync(af[1], &As[wrow * 32 + 16][kk], ALD);
            wmma::load_matrix_sync(bf[0], &Bs[kk][wcol * 32     ], BLD);
            wmma::load_matrix_sync(bf[1], &Bs[kk][wcol * 32 + 16], BLD);
            #pragma unroll
            for (int i = 0; i < 2; i++)
                #pragma unroll
                for (int j = 0; j < 2; j++)
                    wmma::mma_sync(acc[i][j], af[i], bf[j], acc[i][j]);
        }
        __syncthreads();
    }

    // Store. M may not be a multiple of 16 in general: stage partial tiles.
    __syncthreads();                   // As no longer needed; reuse as staging
    float* stage = &As[0][0] + wid * 256;   // 16x16 per warp
    int lane = tid & 31;
    #pragma unroll
    for (int i = 0; i < 2; i++) {
        int r = row0 + wrow * 32 + i * 16;
        #pragma unroll
        for (int j = 0; j < 2; j++) {
            int c = col0 + wcol * 32 + j * 16;
            if (r + 16 <= M) {
                wmma::store_matrix_sync(C + (size_t)r * Nc + c, acc[i][j], Nc,
                                        wmma::mem_row_major);
            } else if (r < M) {
                wmma::store_matrix_sync(stage, acc[i][j], 16, wmma::mem_row_major);
                __syncwarp();
                for (int t = lane; t < 256; t += 32) {
                    int rr = t >> 4, cc = t & 15;
                    if (r + rr < M)
                        C[(size_t)(r + rr) * Nc + c + cc] = stage[t];
                }
                __syncwarp();
            }
        }
    }
}

// -------------------- attention coefficients: [N,H] dot over C --------------
__global__ void alpha_kernel(const float* __restrict__ h,
                             const float* __restrict__ asrc,
                             const float* __restrict__ adst,
                             float* __restrict__ out_s, float* __restrict__ out_d,
                             int N, int H, int C)
{
    int w = (blockIdx.x * blockDim.x + threadIdx.x) >> 5;
    int lane = threadIdx.x & 31;
    if (w >= N * H) return;
    int n = w / H, hh = w - n * H;
    const float* hp = h + (size_t)n * H * C + hh * C;
    float s = 0.f, d = 0.f;
    for (int c = lane; c < C; c += 32) {
        float v = hp[c];
        s += v * asrc[hh * C + c];
        d += v * adst[hh * C + c];
    }
    #pragma unroll
    for (int o = 16; o; o >>= 1) {
        s += __shfl_down_sync(0xffffffffu, s, o);
        d += __shfl_down_sync(0xffffffffu, d, o);
    }
    if (lane == 0) { out_s[w] = s; out_d[w] = d; }
}

// -------------------- CSR build (dst-sorted incoming edge lists) ------------
__global__ void degree_kernel(const int* __restrict__ ei, int* __restrict__ deg, int E)
{
    int e = blockIdx.x * blockDim.x + threadIdx.x;
    if (e < E) atomicAdd(&deg[ei[E + e]], 1);
}

__global__ __launch_bounds__(1024) void scan_kernel(
    const int* __restrict__ deg, int* __restrict__ rowptr,
    int* __restrict__ cursor, int N)
{
    __shared__ int part[1024];
    int tid = threadIdx.x;
    int chunk = (N + 1023) / 1024;
    int b = tid * chunk, e = min(b + chunk, N);
    int s = 0;
    for (int i = b; i < e; i++) s += deg[i];
    part[tid] = s;
    __syncthreads();
    for (int o = 1; o < 1024; o <<= 1) {
        int v = (tid >= o) ? part[tid - o] : 0;
        __syncthreads();
        part[tid] += v;
        __syncthreads();
    }
    int run = tid ? part[tid - 1] : 0;
    for (int i = b; i < e; i++) {
        rowptr[i] = run; cursor[i] = run;
        run += deg[i];
    }
    if (tid == 1023) rowptr[N] = part[1023];
}

__global__ void fill_kernel(const int* __restrict__ ei, int* __restrict__ cursor,
                            int* __restrict__ srcs, int E)
{
    int e = blockIdx.x * blockDim.x + threadIdx.x;
    if (e >= E) return;
    int d = ei[E + e];
    int p = atomicAdd(&cursor[d], 1);
    srcs[p] = ei[e];
}

// ---------- layer-1 GAT aggregation: one warp per node, H=4, C=64 ----------
// Fused BN-stats epilogue: per-block smem accumulation of sum/sumsq over the
// 256 output channels, one fp64 global atomic per channel per block.
__global__ __launch_bounds__(256) void gat_agg4_kernel(
    const int* __restrict__ srcs, const int* __restrict__ rowptr,
    const float* __restrict__ as_, const float* __restrict__ ad_,
    const float* __restrict__ h, float* __restrict__ out,
    double* __restrict__ gsum, double* __restrict__ gsq, int N)
{
    __shared__ float s_sum[256];
    __shared__ float s_sq [256];
    int tid = threadIdx.x;
    s_sum[tid] = 0.f; s_sq[tid] = 0.f;
    __syncthreads();

    int n = (blockIdx.x * blockDim.x + tid) >> 5;
    int lane = tid & 31;
    bool active = (n < N);

    float4 acc0 = make_float4(0, 0, 0, 0), acc1 = acc0;
    if (active) {
        int beg = rowptr[n], end = rowptr[n + 1];
        float4 ad4 = *(const float4*)(ad_ + n * 4);
        float4 asS = *(const float4*)(as_ + n * 4);

        float m0 = NEG_BIG, m1 = NEG_BIG, m2 = NEG_BIG, m3 = NEG_BIG;
        float s0 = 0.f, s1 = 0.f, s2 = 0.f, s3 = 0.f;
        if (lane == 0) {    // self loop
            m0 = lrelu(asS.x + ad4.x); s0 = 1.f;
            m1 = lrelu(asS.y + ad4.y); s1 = 1.f;
            m2 = lrelu(asS.z + ad4.z); s2 = 1.f;
            m3 = lrelu(asS.w + ad4.w); s3 = 1.f;
        }
        for (int e = beg + lane; e < end; e += 32) {
            float4 a4 = *(const float4*)(as_ + srcs[e] * 4);
            float v;
            v = lrelu(a4.x + ad4.x);
            if (v > m0) { s0 = s0 * __expf(m0 - v) + 1.f; m0 = v; } else s0 += __expf(v - m0);
            v = lrelu(a4.y + ad4.y);
            if (v > m1) { s1 = s1 * __expf(m1 - v) + 1.f; m1 = v; } else s1 += __expf(v - m1);
            v = lrelu(a4.z + ad4.z);
            if (v > m2) { s2 = s2 * __expf(m2 - v) + 1.f; m2 = v; } else s2 += __expf(v - m2);
            v = lrelu(a4.w + ad4.w);
            if (v > m3) { s3 = s3 * __expf(m3 - v) + 1.f; m3 = v; } else s3 += __expf(v - m3);
        }
        #pragma unroll
        for (int o = 16; o; o >>= 1) {
            float mm, ss, mn;
            mm = __shfl_xor_sync(0xffffffffu, m0, o); ss = __shfl_xor_sync(0xffffffffu, s0, o);
            mn = fmaxf(m0, mm); s0 = s0 * __expf(m0 - mn) + ss * __expf(mm - mn); m0 = mn;
            mm = __shfl_xor_sync(0xffffffffu, m1, o); ss = __shfl_xor_sync(0xffffffffu, s1, o);
            mn = fmaxf(m1, mm); s1 = s1 * __expf(m1 - mn) + ss * __expf(mm - mn); m1 = mn;
            mm = __shfl_xor_sync(0xffffffffu, m2, o); ss = __shfl_xor_sync(0xffffffffu, s2, o);
            mn = fmaxf(m2, mm); s2 = s2 * __expf(m2 - mn) + ss * __expf(mm - mn); m2 = mn;
            mm = __shfl_xor_sync(0xffffffffu, m3, o); ss = __shfl_xor_sync(0xffffffffu, s3, o);
            mn = fmaxf(m3, mm); s3 = s3 * __expf(m3 - mn) + ss * __expf(mm - mn); m3 = mn;
        }

        int hd = lane >> 3;                          // this lane's head
        float mh  = (hd == 0) ? m0 : (hd == 1) ? m1 : (hd == 2) ? m2 : m3;
        float sh  = (hd == 0) ? s0 : (hd == 1) ? s1 : (hd == 2) ? s2 : s3;
        float adh = (hd == 0) ? ad4.x : (hd == 1) ? ad4.y : (hd == 2) ? ad4.z : ad4.w;
        float inv = 1.f / (sh + 1e-16f);

        for (int e = beg; e < end; e++) {
            int s = srcs[e];
            float v = lrelu(as_[s * 4 + hd] + adh);
            float a = __expf(v - mh) * inv;
            const float4* hp = (const float4*)(h + (size_t)s * 256 + lane * 8);
            float4 v0 = hp[0], v1 = hp[1];
            acc0.x += a * v0.x; acc0.y += a * v0.y; acc0.z += a * v0.z; acc0.w += a * v0.w;
            acc1.x += a * v1.x; acc1.y += a * v1.y; acc1.z += a * v1.z; acc1.w += a * v1.w;
        }
        {   // self loop
            float v = lrelu(as_[n * 4 + hd] + adh);
            float a = __expf(v - mh) * inv;
            const float4* hp = (const float4*)(h + (size_t)n * 256 + lane * 8);
            float4 v0 = hp[0], v1 = hp[1];
            acc0.x += a * v0.x; acc0.y += a * v0.y; acc0.z += a * v0.z; acc0.w += a * v0.w;
            acc1.x += a * v1.x; acc1.y += a * v1.y; acc1.z += a * v1.z; acc1.w += a * v1.w;
        }
        float4* op = (float4*)(out + (size_t)n * 256 + lane * 8);
        op[0] = acc0; op[1] = acc1;

        // stats contribution (channel = lane*8 + j)
        float va[8] = {acc0.x, acc0.y, acc0.z, acc0.w, acc1.x, acc1.y, acc1.z, acc1.w};
        #pragma unroll
        for (int j = 0; j < 8; j++) {
            atomicAdd(&s_sum[lane * 8 + j], va[j]);
            atomicAdd(&s_sq [lane * 8 + j], va[j] * va[j]);
        }
    }
    __syncthreads();
    atomicAdd(&gsum[tid], (double)s_sum[tid]);
    atomicAdd(&gsq [tid], (double)s_sq [tid]);
}

// ---------- layer-2 GAT aggregation: warp per node, H=1, C=64 ---------------
__global__ __launch_bounds__(256) void gat_agg1_kernel(
    const int* __restrict__ srcs, const int* __restrict__ rowptr,
    const float* __restrict__ as_, const float* __restrict__ ad_,
    const float* __restrict__ h, float* __restrict__ out,
    double* __restrict__ gsum, double* __restrict__ gsq, int N)
{
    __shared__ float s_sum[64];
    __shared__ float s_sq [64];
    int tid = threadIdx.x;
    if (tid < 64) { s_sum[tid] = 0.f; s_sq[tid] = 0.f; }
    __syncthreads();

    int n = (blockIdx.x * blockDim.x + tid) >> 5;
    int lane = tid & 31;
    bool active = (n < N);

    if (active) {
        int beg = rowptr[n], end = rowptr[n + 1];
        float ad = ad_[n];
        float as_self = as_[n];

        float m = NEG_BIG, ssum = 0.f;
        if (lane == 0) {
            m = lrelu(as_self + ad); ssum = 1.f;
        }
        for (int e = beg + lane; e < end; e += 32) {
            float v = lrelu(as_[srcs[e]] + ad);
            if (v > m) { ssum = ssum * __expf(m - v) + 1.f; m = v; } else ssum += __expf(v - m);
        }
        #pragma unroll
        for (int o = 16; o; o >>= 1) {
            float m2 = __shfl_xor_sync(0xffffffffu, m, o);
            float s2 = __shfl_xor_sync(0xffffffffu, ssum, o);
            float mn = fmaxf(m, m2);
            ssum = ssum * __expf(m - mn) + s2 * __expf(m2 - mn);
            m = mn;
        }
        float inv = 1.f / (ssum + 1e-16f);

        float acc0 = 0.f, acc1 = 0.f;
        for (int e = beg; e < end; e++) {
            int s = srcs[e];
            float v = lrelu(as_[s] + ad);
            float a = __expf(v - m) * inv;
            const float* hp = h + (size_t)s * 64;
            acc0 += a * hp[lane];
            acc1 += a * hp[lane + 32];
        }
        {   // self loop
            float v = lrelu(as_self + ad);
            float a = __expf(v - m) * inv;
            const float* hp = h + (size_t)n * 64;
            acc0 += a * hp[lane];
            acc1 += a * hp[lane + 32];
        }
        float* op = out + (size_t)n * 64;
        op[lane]      = acc0;
        op[lane + 32] = acc1;

        atomicAdd(&s_sum[lane],      acc0);
        atomicAdd(&s_sq [lane],      acc0 * acc0);
        atomicAdd(&s_sum[lane + 32], acc1);
        atomicAdd(&s_sq [lane + 32], acc1 * acc1);
    }
    __syncthreads();
    if (tid < 64) {
        atomicAdd(&gsum[tid], (double)s_sum[tid]);
        atomicAdd(&gsq [tid], (double)s_sq [tid]);
    }
}

// -------------------- batchnorm stats (fp32 partials, fp64 combine) ---------
__global__ void bn_stats_kernel(const float* __restrict__ x,
                                double* __restrict__ sum, double* __restrict__ sq,
                                int N, int C)
{
    int c = threadIdx.x;        // blockDim.x == C
    float s = 0.f, q = 0.f;
    for (int r = blockIdx.x; r < N; r += gridDim.x) {
        float v = x[(size_t)r * C + c];
        s += v; q += v * v;
    }
    atomicAdd(&sum[c], (double)s);
    atomicAdd(&sq[c], (double)q);
}

__global__ void bn_final_kernel(const double* __restrict__ sum, const double* __restrict__ sq,
                                float* __restrict__ mean, float* __restrict__ rstd,
                                int N, int C)
{
    int c = blockIdx.x * blockDim.x + threadIdx.x;
    if (c >= C) return;
    double mu = sum[c] / N;
    double var = sq[c] / N - mu * mu;
    mean[c] = (float)mu;
    rstd[c] = (float)(1.0 / sqrt(var + (double)EPS_BN));
}

__global__ void bn_apply_kernel(const float* __restrict__ x, float* __restrict__ y,
                                const float* __restrict__ mean, const float* __restrict__ rstd,
                                const float* __restrict__ g, const float* __restrict__ be,
                                int N, int C, int do_elu)
{
    int i4 = blockIdx.x * blockDim.x + threadIdx.x;      // float4 index
    size_t total4 = ((size_t)N * C) >> 2;
    if ((size_t)i4 >= total4) return;
    int c0 = (i4 << 2) % C;
    float4 v = ((const float4*)x)[i4];
    float r[4] = {v.x, v.y, v.z, v.w};
    #pragma unroll
    for (int j = 0; j < 4; j++) {
        int c = c0 + j;
        float t = (r[j] - mean[c]) * rstd[c] * g[c] + be[c];
        if (do_elu) t = t > 0.f ? t : __expf(t) - 1.f;
        r[j] = t;
    }
    ((float4*)y)[i4] = make_float4(r[0], r[1], r[2], r[3]);
}

// -------------------- launch -----------------------------------------------
extern "C" void kernel_launch(void* const* d_in, const int* in_sizes, int n_in,
                              void* d_out, int out_size)
{
    const float* x   = (const float*)d_in[0];
    const int*   ei  = (const int*)  d_in[1];
    const float* W1  = (const float*)d_in[2];
    const float* a1s = (const float*)d_in[3];
    const float* a1d = (const float*)d_in[4];
    // d_in[5] = b1 : followed by BN -> channel-shift invariant -> skipped
    const float* W2  = (const float*)d_in[6];
    const float* a2s = (const float*)d_in[7];
    const float* a2d = (const float*)d_in[8];
    // d_in[9] = b2 : skipped (BN invariance)
    const float* Wp  = (const float*)d_in[10];
    // d_in[11] = bp : skipped (BN invariance)
    const float* g1  = (const float*)d_in[12];
    const float* be1 = (const float*)d_in[13];
    const float* g2  = (const float*)d_in[14];
    const float* be2 = (const float*)d_in[15];
    const float* g3  = (const float*)d_in[16];
    const float* be3 = (const float*)d_in[17];
    float* out = (float*)d_out;

    const int N = in_sizes[0] / IN_DIM;       // 50000
    const int E = in_sizes[1] / 2;            // 800000

    float *h1, *o1, *as1, *ad1;
    float *h2, *o2, *as2, *ad2, *proj, *meanp, *rstdp, *meanp2, *rstdp2;
    int *deg, *rowptr, *cursor, *srcs;
    double *sump, *sqp, *sump2, *sqp2;
    cudaGetSymbolAddress((void**)&h1,   g_h1);
    cudaGetSymbolAddress((void**)&o1,   g_o1);
    cudaGetSymbolAddress((void**)&as1,  g_as1);
    cudaGetSymbolAddress((void**)&ad1,  g_ad1);
    cudaGetSymbolAddress((void**)&h2,   g_h2);
    cudaGetSymbolAddress((void**)&o2,   g_o2);
    cudaGetSymbolAddress((void**)&as2,  g_as2);
    cudaGetSymbolAddress((void**)&ad2,  g_ad2);
    cudaGetSymbolAddress((void**)&proj, g_proj);
    cudaGetSymbolAddress((void**)&deg,    g_deg);
    cudaGetSymbolAddress((void**)&rowptr, g_rowptr);
    cudaGetSymbolAddress((void**)&cursor, g_cursor);
    cudaGetSymbolAddress((void**)&srcs,   g_srcs);
    cudaGetSymbolAddress((void**)&sump,  g_sum);
    cudaGetSymbolAddress((void**)&sqp,   g_sq);
    cudaGetSymbolAddress((void**)&meanp, g_mean);
    cudaGetSymbolAddress((void**)&rstdp, g_rstd);
    cudaGetSymbolAddress((void**)&sump2,  g_sum2);
    cudaGetSymbolAddress((void**)&sqp2,   g_sq2);
    cudaGetSymbolAddress((void**)&meanp2, g_mean2);
    cudaGetSymbolAddress((void**)&rstdp2, g_rstd2);

    cudaStream_t st = 0;

    // zero stat accumulators up front
    cudaMemsetAsync(sump,  0, D1 * sizeof(double), st);
    cudaMemsetAsync(sqp,   0, D1 * sizeof(double), st);
    cudaMemsetAsync(sump2, 0, D2 * sizeof(double), st);
    cudaMemsetAsync(sqp2,  0, D2 * sizeof(double), st);

    // ---------------- CSR build (shared by both layers) ---------------------
    cudaMemsetAsync(deg, 0, (size_t)N * sizeof(int), st);
    degree_kernel<<<(E + 255) / 256, 256, 0, st>>>(ei, deg, E);
    scan_kernel<<<1, 1024, 0, st>>>(deg, rowptr, cursor, N);
    fill_kernel<<<(E + 255) / 256, 256, 0, st>>>(ei, cursor, srcs, E);

    // ---------------- layer 1: GATConv(128 -> 4x64, concat) ----------------
    {
        dim3 grid(D1 / GBN, (N + GBM - 1) / GBM);
        gemm_tf32_kernel<false><<<grid, 256, 0, st>>>(x, W1, h1, N, D1, IN_DIM,
                                                      nullptr, nullptr, nullptr, nullptr);
    }
    alpha_kernel<<<(N * H1N * 32 + 255) / 256, 256, 0, st>>>(h1, a1s, a1d, as1, ad1, N, H1N, C1N);
    // aggregation + fused BN1 stats
    gat_agg4_kernel<<<(N * 32 + 255) / 256, 256, 0, st>>>(
        srcs, rowptr, as1, ad1, h1, o1, sump, sqp, N);
    bn_final_kernel<<<1, D1, 0, st>>>(sump, sqp, meanp, rstdp, N, D1);

    // ---------------- layer 2: GATConv(256 -> 64, H=1) ---------------------
    // BN1+ELU fused into the A-tile load (A = o1, per-K-channel affine).
    {
        dim3 grid(D2 / GBN, (N + GBM - 1) / GBM);
        gemm_tf32_kernel<true><<<grid, 256, 0, st>>>(o1, W2, h2, N, D2, D1,
                                                     meanp, rstdp, g1, be1);
    }
    alpha_kernel<<<(N * 32 + 255) / 256, 256, 0, st>>>(h2, a2s, a2d, as2, ad2, N, 1, D2);
    // aggregation + fused BN2 stats
    gat_agg1_kernel<<<(N * 32 + 255) / 256, 256, 0, st>>>(
        srcs, rowptr, as2, ad2, h2, o2, sump2, sqp2, N);
    bn_final_kernel<<<1, D2, 0, st>>>(sump2, sqp2, meanp2, rstdp2, N, D2);

    // ---------------- projection 64 -> 128 + BN3 ---------------------------
    // BN2+ELU fused into the A-tile load (A = o2).
    {
        dim3 grid(IN_DIM / GBN, (N + GBM - 1) / GBM);
        gemm_tf32_kernel<true><<<grid, 256, 0, st>>>(o2, Wp, proj, N, IN_DIM, D2,
                                                     meanp2, rstdp2, g2, be2);
    }
    cudaMemsetAsync(sump, 0, IN_DIM * sizeof(double), st);
    cudaMemsetAsync(sqp,  0, IN_DIM * sizeof(double), st);
    bn_stats_kernel<<<512, IN_DIM, 0, st>>>(proj, sump, sqp, N, IN_DIM);
    bn_final_kernel<<<1, IN_DIM, 0, st>>>(sump, sqp, meanp, rstdp, N, IN_DIM);
    bn_apply_kernel<<<(((size_t)N * IN_DIM / 4) + 255) / 256, 256, 0, st>>>(
        proj, out, meanp, rstdp, g3, be3, N, IN_DIM, 0);
}

// round 11
// speedup vs baseline: 1.5029x; 1.5029x over previous
#include <cuda_runtime.h>
#include <cuda_bf16.h>
#include <mma.h>
#include <math.h>

using namespace nvcuda;

// Problem constants (shapes fixed by the dataset).
#define NN      50000
#define EEDGES  800000
#define IN_DIM  128
#define H1N     4
#define C1N     64
#define D1      (H1N * C1N)          // 256
#define D2      64
#define EPS_BN  1e-5f
#define NEG_SLOPE 0.2f
#define NEG_BIG  (-1e30f)

// -------------------- scratch (static __device__, no allocs) ----------------
__device__ float    g_h1  [NN * D1];       // x@W1 (layer-1 lin output)
__device__ float    g_o1  [NN * D1];       // GAT1 aggregation output (pre-BN)
__device__ float    g_as1 [NN * H1N];
__device__ float    g_ad1 [NN * H1N];
__device__ float    g_h2  [NN * D2];       // layer-2 lin output
__device__ float    g_o2  [NN * D2];       // GAT2 aggregation output (pre-BN)
__device__ float    g_as2 [NN];
__device__ float    g_ad2 [NN];
__device__ float    g_proj[NN * IN_DIM];
__device__ int      g_deg [NN];
__device__ int      g_rowptr[NN + 1];
__device__ int      g_cursor[NN];
__device__ int      g_srcs[EEDGES];
__device__ double   g_sum [256];
__device__ double   g_sq  [256];
__device__ float    g_mean[256];
__device__ float    g_rstd[256];
__device__ double   g_sum2[64];
__device__ double   g_sq2 [64];
__device__ float    g_mean2[64];
__device__ float    g_rstd2[64];

__device__ __forceinline__ float lrelu(float v) {
    return v > 0.f ? v : NEG_SLOPE * v;
}
__device__ __forceinline__ float bn_elu(float v, float mu, float rs, float ga, float bb) {
    float t = (v - mu) * rs * ga + bb;
    return t > 0.f ? t : __expf(t) - 1.f;
}

// ------------- GEMM (TF32 tensor cores): C[M,Nc] = A[M,K] @ B[K,Nc] ---------
// BM=128, BN=64, BK=16. 256 threads = 8 warps in 4x2; each warp 32x32 output
// via 2x2 wmma m16n16k8 accumulators. A,B staged in smem as tf32.
// FUSE_BN: apply per-K-channel BN+ELU to A elements while staging.
#define GBM 128
#define GBN 64
#define ALD 20      // A smem leading dim (mult of 4)
#define BLD 68      // B smem leading dim (mult of 4)
template<bool FUSE_BN>
__global__ __launch_bounds__(256) void gemm_tf32_kernel(
    const float* __restrict__ A, const float* __restrict__ B,
    float* __restrict__ C, int M, int Nc, int K,
    const float* __restrict__ bn_mean, const float* __restrict__ bn_rstd,
    const float* __restrict__ bn_g,    const float* __restrict__ bn_be)
{
    __shared__ float As[GBM][ALD];   // 128x16 tile (tf32 values)
    __shared__ float Bs[16][BLD];    // 16x64 tile
    int tid = threadIdx.x;
    int wid  = tid >> 5;
    int wrow = wid >> 1;             // 0..3 -> 32-row strip
    int wcol = wid & 1;              // 0..1 -> 32-col strip
    int row0 = blockIdx.y * GBM, col0 = blockIdx.x * GBN;

    wmma::fragment<wmma::accumulator, 16, 16, 8, float> acc[2][2];
    #pragma unroll
    for (int i = 0; i < 2; i++)
        #pragma unroll
        for (int j = 0; j < 2; j++) wmma::fill_fragment(acc[i][j], 0.f);

    for (int k0 = 0; k0 < K; k0 += 16) {
        {   // A tile: 128 rows x 16 k. Each thread: one row, 8 k (2 float4).
            int r  = tid >> 1;
            int c8 = (tid & 1) * 8;
            float4 v0 = make_float4(0, 0, 0, 0), v1 = v0;
            if (row0 + r < M) {
                const float* ap = A + (size_t)(row0 + r) * K + k0 + c8;
                v0 = *(const float4*)ap;
                v1 = *(const float4*)(ap + 4);
            }
            float av[8] = {v0.x, v0.y, v0.z, v0.w, v1.x, v1.y, v1.z, v1.w};
            if (FUSE_BN) {
                #pragma unroll
                for (int j = 0; j < 8; j++) {
                    int c = k0 + c8 + j;
                    av[j] = bn_elu(av[j], bn_mean[c], bn_rstd[c], bn_g[c], bn_be[c]);
                }
            }
            #pragma unroll
            for (int j = 0; j < 8; j++)
                As[r][c8 + j] = wmma::__float_to_tf32(av[j]);
        }
        {   // B tile: 16 k x 64 cols. Each thread one float4.
            int r  = tid >> 4;
            int c4 = (tid & 15) * 4;
            float4 v = *(const float4*)(B + (size_t)(k0 + r) * Nc + col0 + c4);
            Bs[r][c4 + 0] = wmma::__float_to_tf32(v.x);
            Bs[r][c4 + 1] = wmma::__float_to_tf32(v.y);
            Bs[r][c4 + 2] = wmma::__float_to_tf32(v.z);
            Bs[r][c4 + 3] = wmma::__float_to_tf32(v.w);
        }
        __syncthreads();
        #pragma unroll
        for (int kk = 0; kk < 16; kk += 8) {
            wmma::fragment<wmma::matrix_a, 16, 16, 8, wmma::precision::tf32, wmma::row_major> af[2];
            wmma::fragment<wmma::matrix_b, 16, 16, 8, wmma::precision::tf32, wmma::row_major> bf[2];
            wmma::load_matrix_sync(af[0], &As[wrow * 32     ][kk], ALD);
            wmma::load_matrix_sync(af[1], &As[wrow * 32 + 16][kk], ALD);
            wmma::load_matrix_sync(bf[0], &Bs[kk][wcol * 32     ], BLD);
            wmma::load_matrix_sync(bf[1], &Bs[kk][wcol * 32 + 16], BLD);
            #pragma unroll
            for (int i = 0; i < 2; i++)
                #pragma unroll
                for (int j = 0; j < 2; j++)
                    wmma::mma_sync(acc[i][j], af[i], bf[j], acc[i][j]);
        }
        __syncthreads();
    }

    // Store. M may not be a multiple of 16 in general: stage partial tiles.
    __syncthreads();                   // As no longer needed; reuse as staging
    float* stage = &As[0][0] + wid * 256;   // 16x16 per warp
    int lane = tid & 31;
    #pragma unroll
    for (int i = 0; i < 2; i++) {
        int r = row0 + wrow * 32 + i * 16;
        #pragma unroll
        for (int j = 0; j < 2; j++) {
            int c = col0 + wcol * 32 + j * 16;
            if (r + 16 <= M) {
                wmma::store_matrix_sync(C + (size_t)r * Nc + c, acc[i][j], Nc,
                                        wmma::mem_row_major);
            } else if (r < M) {
                wmma::store_matrix_sync(stage, acc[i][j], 16, wmma::mem_row_major);
                __syncwarp();
                for (int t = lane; t < 256; t += 32) {
                    int rr = t >> 4, cc = t & 15;
                    if (r + rr < M)
                        C[(size_t)(r + rr) * Nc + c + cc] = stage[t];
                }
                __syncwarp();
            }
        }
    }
}

// -------------------- attention coefficients: [N,H] dot over C --------------
__global__ void alpha_kernel(const float* __restrict__ h,
                             const float* __restrict__ asrc,
                             const float* __restrict__ adst,
                             float* __restrict__ out_s, float* __restrict__ out_d,
                             int N, int H, int C)
{
    int w = (blockIdx.x * blockDim.x + threadIdx.x) >> 5;
    int lane = threadIdx.x & 31;
    if (w >= N * H) return;
    int n = w / H, hh = w - n * H;
    const float* hp = h + (size_t)n * H * C + hh * C;
    float s = 0.f, d = 0.f;
    for (int c = lane; c < C; c += 32) {
        float v = hp[c];
        s += v * asrc[hh * C + c];
        d += v * adst[hh * C + c];
    }
    #pragma unroll
    for (int o = 16; o; o >>= 1) {
        s += __shfl_down_sync(0xffffffffu, s, o);
        d += __shfl_down_sync(0xffffffffu, d, o);
    }
    if (lane == 0) { out_s[w] = s; out_d[w] = d; }
}

// -------------------- CSR build (dst-sorted incoming edge lists) ------------
__global__ void degree_kernel(const int* __restrict__ ei, int* __restrict__ deg, int E)
{
    int e = blockIdx.x * blockDim.x + threadIdx.x;
    if (e < E) atomicAdd(&deg[ei[E + e]], 1);
}

__global__ __launch_bounds__(1024) void scan_kernel(
    const int* __restrict__ deg, int* __restrict__ rowptr,
    int* __restrict__ cursor, int N)
{
    __shared__ int part[1024];
    int tid = threadIdx.x;
    int chunk = (N + 1023) / 1024;
    int b = tid * chunk, e = min(b + chunk, N);
    int s = 0;
    for (int i = b; i < e; i++) s += deg[i];
    part[tid] = s;
    __syncthreads();
    for (int o = 1; o < 1024; o <<= 1) {
        int v = (tid >= o) ? part[tid - o] : 0;
        __syncthreads();
        part[tid] += v;
        __syncthreads();
    }
    int run = tid ? part[tid - 1] : 0;
    for (int i = b; i < e; i++) {
        rowptr[i] = run; cursor[i] = run;
        run += deg[i];
    }
    if (tid == 1023) rowptr[N] = part[1023];
}

__global__ void fill_kernel(const int* __restrict__ ei, int* __restrict__ cursor,
                            int* __restrict__ srcs, int E)
{
    int e = blockIdx.x * blockDim.x + threadIdx.x;
    if (e >= E) return;
    int d = ei[E + e];
    int p = atomicAdd(&cursor[d], 1);
    srcs[p] = ei[e];
}

// ---------- layer-1 GAT aggregation: one warp per node, H=4, C=64 ----------
__global__ void gat_agg4_kernel(const int* __restrict__ srcs,
                                const int* __restrict__ rowptr,
                                const float* __restrict__ as_,
                                const float* __restrict__ ad_,
                                const float* __restrict__ h,
                                float* __restrict__ out, int N)
{
    int n = (blockIdx.x * blockDim.x + threadIdx.x) >> 5;
    int lane = threadIdx.x & 31;
    if (n >= N) return;
    int beg = rowptr[n], end = rowptr[n + 1];

    float4 ad4 = *(const float4*)(ad_ + n * 4);
    float4 asS = *(const float4*)(as_ + n * 4);

    float m0 = NEG_BIG, m1 = NEG_BIG, m2 = NEG_BIG, m3 = NEG_BIG;
    float s0 = 0.f, s1 = 0.f, s2 = 0.f, s3 = 0.f;
    if (lane == 0) {    // self loop
        m0 = lrelu(asS.x + ad4.x); s0 = 1.f;
        m1 = lrelu(asS.y + ad4.y); s1 = 1.f;
        m2 = lrelu(asS.z + ad4.z); s2 = 1.f;
        m3 = lrelu(asS.w + ad4.w); s3 = 1.f;
    }
    for (int e = beg + lane; e < end; e += 32) {
        float4 a4 = *(const float4*)(as_ + srcs[e] * 4);
        float v;
        v = lrelu(a4.x + ad4.x);
        if (v > m0) { s0 = s0 * __expf(m0 - v) + 1.f; m0 = v; } else s0 += __expf(v - m0);
        v = lrelu(a4.y + ad4.y);
        if (v > m1) { s1 = s1 * __expf(m1 - v) + 1.f; m1 = v; } else s1 += __expf(v - m1);
        v = lrelu(a4.z + ad4.z);
        if (v > m2) { s2 = s2 * __expf(m2 - v) + 1.f; m2 = v; } else s2 += __expf(v - m2);
        v = lrelu(a4.w + ad4.w);
        if (v > m3) { s3 = s3 * __expf(m3 - v) + 1.f; m3 = v; } else s3 += __expf(v - m3);
    }
    #pragma unroll
    for (int o = 16; o; o >>= 1) {
        float mm, ss, mn;
        mm = __shfl_xor_sync(0xffffffffu, m0, o); ss = __shfl_xor_sync(0xffffffffu, s0, o);
        mn = fmaxf(m0, mm); s0 = s0 * __expf(m0 - mn) + ss * __expf(mm - mn); m0 = mn;
        mm = __shfl_xor_sync(0xffffffffu, m1, o); ss = __shfl_xor_sync(0xffffffffu, s1, o);
        mn = fmaxf(m1, mm); s1 = s1 * __expf(m1 - mn) + ss * __expf(mm - mn); m1 = mn;
        mm = __shfl_xor_sync(0xffffffffu, m2, o); ss = __shfl_xor_sync(0xffffffffu, s2, o);
        mn = fmaxf(m2, mm); s2 = s2 * __expf(m2 - mn) + ss * __expf(mm - mn); m2 = mn;
        mm = __shfl_xor_sync(0xffffffffu, m3, o); ss = __shfl_xor_sync(0xffffffffu, s3, o);
        mn = fmaxf(m3, mm); s3 = s3 * __expf(m3 - mn) + ss * __expf(mm - mn); m3 = mn;
    }

    int hd = lane >> 3;                          // this lane's head
    float mh  = (hd == 0) ? m0 : (hd == 1) ? m1 : (hd == 2) ? m2 : m3;
    float sh  = (hd == 0) ? s0 : (hd == 1) ? s1 : (hd == 2) ? s2 : s3;
    float adh = (hd == 0) ? ad4.x : (hd == 1) ? ad4.y : (hd == 2) ? ad4.z : ad4.w;
    float inv = 1.f / (sh + 1e-16f);

    float4 acc0 = make_float4(0, 0, 0, 0), acc1 = acc0;
    for (int e = beg; e < end; e++) {
        int s = srcs[e];
        float v = lrelu(as_[s * 4 + hd] + adh);
        float a = __expf(v - mh) * inv;
        const float4* hp = (const float4*)(h + (size_t)s * 256 + lane * 8);
        float4 v0 = hp[0], v1 = hp[1];
        acc0.x += a * v0.x; acc0.y += a * v0.y; acc0.z += a * v0.z; acc0.w += a * v0.w;
        acc1.x += a * v1.x; acc1.y += a * v1.y; acc1.z += a * v1.z; acc1.w += a * v1.w;
    }
    {   // self loop
        float v = lrelu(as_[n * 4 + hd] + adh);
        float a = __expf(v - mh) * inv;
        const float4* hp = (const float4*)(h + (size_t)n * 256 + lane * 8);
        float4 v0 = hp[0], v1 = hp[1];
        acc0.x += a * v0.x; acc0.y += a * v0.y; acc0.z += a * v0.z; acc0.w += a * v0.w;
        acc1.x += a * v1.x; acc1.y += a * v1.y; acc1.z += a * v1.z; acc1.w += a * v1.w;
    }
    float4* op = (float4*)(out + (size_t)n * 256 + lane * 8);
    op[0] = acc0; op[1] = acc1;
}

// ---------- layer-2 GAT aggregation: warp per node, H=1, C=64 ---------------
__global__ void gat_agg1_kernel(const int* __restrict__ srcs,
                                const int* __restrict__ rowptr,
                                const float* __restrict__ as_,
                                const float* __restrict__ ad_,
                                const float* __restrict__ h,
                                float* __restrict__ out, int N)
{
    int n = (blockIdx.x * blockDim.x + threadIdx.x) >> 5;
    int lane = threadIdx.x & 31;
    if (n >= N) return;
    int beg = rowptr[n], end = rowptr[n + 1];
    float ad = ad_[n];
    float as_self = as_[n];

    float m = NEG_BIG, ssum = 0.f;
    if (lane == 0) {
        m = lrelu(as_self + ad); ssum = 1.f;
    }
    for (int e = beg + lane; e < end; e += 32) {
        float v = lrelu(as_[srcs[e]] + ad);
        if (v > m) { ssum = ssum * __expf(m - v) + 1.f; m = v; } else ssum += __expf(v - m);
    }
    #pragma unroll
    for (int o = 16; o; o >>= 1) {
        float m2 = __shfl_xor_sync(0xffffffffu, m, o);
        float s2 = __shfl_xor_sync(0xffffffffu, ssum, o);
        float mn = fmaxf(m, m2);
        ssum = ssum * __expf(m - mn) + s2 * __expf(m2 - mn);
        m = mn;
    }
    float inv = 1.f / (ssum + 1e-16f);

    float acc0 = 0.f, acc1 = 0.f;
    for (int e = beg; e < end; e++) {
        int s = srcs[e];
        float v = lrelu(as_[s] + ad);
        float a = __expf(v - m) * inv;
        const float* hp = h + (size_t)s * 64;
        acc0 += a * hp[lane];
        acc1 += a * hp[lane + 32];
    }
    {   // self loop
        float v = lrelu(as_self + ad);
        float a = __expf(v - m) * inv;
        const float* hp = h + (size_t)n * 64;
        acc0 += a * hp[lane];
        acc1 += a * hp[lane + 32];
    }
    float* op = out + (size_t)n * 64;
    op[lane]      = acc0;
    op[lane + 32] = acc1;
}

// -------------------- batchnorm stats (fp32 partials, fp64 combine) ---------
__global__ void bn_stats_kernel(const float* __restrict__ x,
                                double* __restrict__ sum, double* __restrict__ sq,
                                int N, int C)
{
    int c = threadIdx.x;        // blockDim.x == C
    float s = 0.f, q = 0.f;
    for (int r = blockIdx.x; r < N; r += gridDim.x) {
        float v = x[(size_t)r * C + c];
        s += v; q += v * v;
    }
    atomicAdd(&sum[c], (double)s);
    atomicAdd(&sq[c], (double)q);
}

__global__ void bn_final_kernel(const double* __restrict__ sum, const double* __restrict__ sq,
                                float* __restrict__ mean, float* __restrict__ rstd,
                                int N, int C)
{
    int c = blockIdx.x * blockDim.x + threadIdx.x;
    if (c >= C) return;
    double mu = sum[c] / N;
    double var = sq[c] / N - mu * mu;
    mean[c] = (float)mu;
    rstd[c] = (float)(1.0 / sqrt(var + (double)EPS_BN));
}

__global__ void bn_apply_kernel(const float* __restrict__ x, float* __restrict__ y,
                                const float* __restrict__ mean, const float* __restrict__ rstd,
                                const float* __restrict__ g, const float* __restrict__ be,
                                int N, int C, int do_elu)
{
    int i4 = blockIdx.x * blockDim.x + threadIdx.x;      // float4 index
    size_t total4 = ((size_t)N * C) >> 2;
    if ((size_t)i4 >= total4) return;
    int c0 = (i4 << 2) % C;
    float4 v = ((const float4*)x)[i4];
    float r[4] = {v.x, v.y, v.z, v.w};
    #pragma unroll
    for (int j = 0; j < 4; j++) {
        int c = c0 + j;
        float t = (r[j] - mean[c]) * rstd[c] * g[c] + be[c];
        if (do_elu) t = t > 0.f ? t : __expf(t) - 1.f;
        r[j] = t;
    }
    ((float4*)y)[i4] = make_float4(r[0], r[1], r[2], r[3]);
}

// -------------------- launch -----------------------------------------------
extern "C" void kernel_launch(void* const* d_in, const int* in_sizes, int n_in,
                              void* d_out, int out_size)
{
    const float* x   = (const float*)d_in[0];
    const int*   ei  = (const int*)  d_in[1];
    const float* W1  = (const float*)d_in[2];
    const float* a1s = (const float*)d_in[3];
    const float* a1d = (const float*)d_in[4];
    // d_in[5] = b1 : followed by BN -> channel-shift invariant -> skipped
    const float* W2  = (const float*)d_in[6];
    const float* a2s = (const float*)d_in[7];
    const float* a2d = (const float*)d_in[8];
    // d_in[9] = b2 : skipped (BN invariance)
    const float* Wp  = (const float*)d_in[10];
    // d_in[11] = bp : skipped (BN invariance)
    const float* g1  = (const float*)d_in[12];
    const float* be1 = (const float*)d_in[13];
    const float* g2  = (const float*)d_in[14];
    const float* be2 = (const float*)d_in[15];
    const float* g3  = (const float*)d_in[16];
    const float* be3 = (const float*)d_in[17];
    float* out = (float*)d_out;

    const int N = in_sizes[0] / IN_DIM;       // 50000
    const int E = in_sizes[1] / 2;            // 800000

    float *h1, *o1, *as1, *ad1;
    float *h2, *o2, *as2, *ad2, *proj, *meanp, *rstdp, *meanp2, *rstdp2;
    int *deg, *rowptr, *cursor, *srcs;
    double *sump, *sqp, *sump2, *sqp2;
    cudaGetSymbolAddress((void**)&h1,   g_h1);
    cudaGetSymbolAddress((void**)&o1,   g_o1);
    cudaGetSymbolAddress((void**)&as1,  g_as1);
    cudaGetSymbolAddress((void**)&ad1,  g_ad1);
    cudaGetSymbolAddress((void**)&h2,   g_h2);
    cudaGetSymbolAddress((void**)&o2,   g_o2);
    cudaGetSymbolAddress((void**)&as2,  g_as2);
    cudaGetSymbolAddress((void**)&ad2,  g_ad2);
    cudaGetSymbolAddress((void**)&proj, g_proj);
    cudaGetSymbolAddress((void**)&deg,    g_deg);
    cudaGetSymbolAddress((void**)&rowptr, g_rowptr);
    cudaGetSymbolAddress((void**)&cursor, g_cursor);
    cudaGetSymbolAddress((void**)&srcs,   g_srcs);
    cudaGetSymbolAddress((void**)&sump,  g_sum);
    cudaGetSymbolAddress((void**)&sqp,   g_sq);
    cudaGetSymbolAddress((void**)&meanp, g_mean);
    cudaGetSymbolAddress((void**)&rstdp, g_rstd);
    cudaGetSymbolAddress((void**)&sump2,  g_sum2);
    cudaGetSymbolAddress((void**)&sqp2,   g_sq2);
    cudaGetSymbolAddress((void**)&meanp2, g_mean2);
    cudaGetSymbolAddress((void**)&rstdp2, g_rstd2);

    cudaStream_t st = 0;

    // zero stat accumulators up front
    cudaMemsetAsync(sump,  0, D1 * sizeof(double), st);
    cudaMemsetAsync(sqp,   0, D1 * sizeof(double), st);
    cudaMemsetAsync(sump2, 0, D2 * sizeof(double), st);
    cudaMemsetAsync(sqp2,  0, D2 * sizeof(double), st);

    // ---------------- CSR build (shared by both layers) ---------------------
    cudaMemsetAsync(deg, 0, (size_t)N * sizeof(int), st);
    degree_kernel<<<(E + 255) / 256, 256, 0, st>>>(ei, deg, E);
    scan_kernel<<<1, 1024, 0, st>>>(deg, rowptr, cursor, N);
    fill_kernel<<<(E + 255) / 256, 256, 0, st>>>(ei, cursor, srcs, E);

    // ---------------- layer 1: GATConv(128 -> 4x64, concat) ----------------
    {
        dim3 grid(D1 / GBN, (N + GBM - 1) / GBM);
        gemm_tf32_kernel<false><<<grid, 256, 0, st>>>(x, W1, h1, N, D1, IN_DIM,
                                                      nullptr, nullptr, nullptr, nullptr);
    }
    alpha_kernel<<<(N * H1N * 32 + 255) / 256, 256, 0, st>>>(h1, a1s, a1d, as1, ad1, N, H1N, C1N);
    gat_agg4_kernel<<<(N * 32 + 255) / 256, 256, 0, st>>>(
        srcs, rowptr, as1, ad1, h1, o1, N);

    // BN1 stats on o1 (512-block fan-in; apply is fused into gemm2's A load)
    bn_stats_kernel<<<512, D1, 0, st>>>(o1, sump, sqp, N, D1);
    bn_final_kernel<<<1, D1, 0, st>>>(sump, sqp, meanp, rstdp, N, D1);

    // ---------------- layer 2: GATConv(256 -> 64, H=1) ---------------------
    // BN1+ELU fused into the A-tile load (A = o1, per-K-channel affine).
    {
        dim3 grid(D2 / GBN, (N + GBM - 1) / GBM);
        gemm_tf32_kernel<true><<<grid, 256, 0, st>>>(o1, W2, h2, N, D2, D1,
                                                     meanp, rstdp, g1, be1);
    }
    alpha_kernel<<<(N * 32 + 255) / 256, 256, 0, st>>>(h2, a2s, a2d, as2, ad2, N, 1, D2);
    gat_agg1_kernel<<<(N * 32 + 255) / 256, 256, 0, st>>>(
        srcs, rowptr, as2, ad2, h2, o2, N);

    // BN2 stats on o2 (apply fused into gemm3's A load)
    bn_stats_kernel<<<512, D2, 0, st>>>(o2, sump2, sqp2, N, D2);
    bn_final_kernel<<<1, D2, 0, st>>>(sump2, sqp2, meanp2, rstdp2, N, D2);

    // ---------------- projection 64 -> 128 + BN3 ---------------------------
    // BN2+ELU fused into the A-tile load (A = o2).
    {
        dim3 grid(IN_DIM / GBN, (N + GBM - 1) / GBM);
        gemm_tf32_kernel<true><<<grid, 256, 0, st>>>(o2, Wp, proj, N, IN_DIM, D2,
                                                     meanp2, rstdp2, g2, be2);
    }
    cudaMemsetAsync(sump, 0, IN_DIM * sizeof(double), st);
    cudaMemsetAsync(sqp,  0, IN_DIM * sizeof(double), st);
    bn_stats_kernel<<<512, IN_DIM, 0, st>>>(proj, sump, sqp, N, IN_DIM);
    bn_final_kernel<<<1, IN_DIM, 0, st>>>(sump, sqp, meanp, rstdp, N, IN_DIM);
    bn_apply_kernel<<<(((size_t)N * IN_DIM / 4) + 255) / 256, 256, 0, st>>>(
        proj, out, meanp, rstdp, g3, be3, N, IN_DIM, 0);
}

// round 12
// speedup vs baseline: 1.5779x; 1.0499x over previous
#include <cuda_runtime.h>
#include <cuda_bf16.h>
#include <mma.h>
#include <math.h>

using namespace nvcuda;

// Problem constants (shapes fixed by the dataset).
#define NN      50000
#define EEDGES  800000
#define IN_DIM  128
#define H1N     4
#define C1N     64
#define D1      (H1N * C1N)          // 256
#define D2      64
#define EPS_BN  1e-5f
#define NEG_SLOPE 0.2f
#define NEG_BIG  (-1e30f)

// -------------------- scratch (static __device__, no allocs) ----------------
__device__ float    g_h1  [NN * D1];
__device__ float    g_o1  [NN * D1];
__device__ float    g_as1 [NN * H1N];
__device__ float    g_ad1 [NN * H1N];
__device__ float    g_h2  [NN * D2];
__device__ float    g_o2  [NN * D2];
__device__ float    g_as2 [NN];
__device__ float    g_ad2 [NN];
__device__ float    g_proj[NN * IN_DIM];
__device__ int      g_deg [NN];
__device__ int      g_rowptr[NN + 1];
__device__ int      g_cursor[NN];
__device__ int      g_srcs[EEDGES];
__device__ double   g_sum [256];
__device__ double   g_sq  [256];
__device__ float    g_mean[256];
__device__ float    g_rstd[256];
__device__ double   g_sum2[64];
__device__ double   g_sq2 [64];
__device__ float    g_mean2[64];
__device__ float    g_rstd2[64];

__device__ __forceinline__ float lrelu(float v) {
    return v > 0.f ? v : NEG_SLOPE * v;
}
__device__ __forceinline__ float bn_elu(float v, float mu, float rs, float ga, float bb) {
    float t = (v - mu) * rs * ga + bb;
    return t > 0.f ? t : __expf(t) - 1.f;
}

// ------------- GEMM (TF32 tensor cores): C[M,Nc] = A[M,K] @ B[K,Nc] ---------
// BM=128, BN=64, BK=16. 256 threads = 8 warps in 4x2; each warp 32x32 output
// via 2x2 wmma m16n16k8 accumulators. Double-buffered smem (1 sync per tile).
// FUSE_BN:    apply per-K-channel BN+ELU to A while staging.
// FUSE_ALPHA: block's 64 columns == one head; epilogue computes
//             as/ad[row*AH + blockIdx.x] = dot(C_row_segment, a_src/a_dst).
#define GBM 128
#define GBN 64
#define ALD 20      // A smem leading dim (mult of 4)
#define BLD 68      // B smem leading dim (mult of 4)
template<bool FUSE_BN, bool FUSE_ALPHA>
__global__ __launch_bounds__(256) void gemm_tf32_kernel(
    const float* __restrict__ A, const float* __restrict__ B,
    float* __restrict__ C, int M, int Nc, int K,
    const float* __restrict__ bn_mean, const float* __restrict__ bn_rstd,
    const float* __restrict__ bn_g,    const float* __restrict__ bn_be,
    const float* __restrict__ a_src,   const float* __restrict__ a_dst,
    float* __restrict__ out_s, float* __restrict__ out_d, int AH)
{
    __shared__ float As[2][GBM][ALD];   // 128x16 tiles (tf32 values)
    __shared__ float Bs[2][16][BLD];    // 16x64 tiles
    int tid = threadIdx.x;
    int wid  = tid >> 5;
    int wrow = wid >> 1;             // 0..3 -> 32-row strip
    int wcol = wid & 1;              // 0..1 -> 32-col strip
    int row0 = blockIdx.y * GBM, col0 = blockIdx.x * GBN;

    // per-thread load coords
    int ar  = tid >> 1;              // A: row within tile
    int ac8 = (tid & 1) * 8;         // A: k offset (8 floats)
    int br  = tid >> 4;              // B: k row
    int bc4 = (tid & 15) * 4;        // B: col offset (4 floats)
    bool arow_ok = (row0 + ar < M);
    const float* aptr = A + (size_t)(row0 + ar) * K + ac8;
    const float* bptr = B + (size_t)br * Nc + col0 + bc4;

    wmma::fragment<wmma::accumulator, 16, 16, 8, float> acc[2][2];
    #pragma unroll
    for (int i = 0; i < 2; i++)
        #pragma unroll
        for (int j = 0; j < 2; j++) wmma::fill_fragment(acc[i][j], 0.f);

    int ntiles = K >> 4;

    // ---- stage tile 0 ----
    {
        float4 v0 = make_float4(0,0,0,0), v1 = v0;
        if (arow_ok) { v0 = *(const float4*)aptr; v1 = *(const float4*)(aptr + 4); }
        float av[8] = {v0.x,v0.y,v0.z,v0.w,v1.x,v1.y,v1.z,v1.w};
        if (FUSE_BN) {
            #pragma unroll
            for (int j = 0; j < 8; j++) {
                int c = ac8 + j;
                av[j] = bn_elu(av[j], bn_mean[c], bn_rstd[c], bn_g[c], bn_be[c]);
            }
        }
        #pragma unroll
        for (int j = 0; j < 8; j++) As[0][ar][ac8 + j] = wmma::__float_to_tf32(av[j]);
        float4 bv = *(const float4*)bptr;
        Bs[0][br][bc4 + 0] = wmma::__float_to_tf32(bv.x);
        Bs[0][br][bc4 + 1] = wmma::__float_to_tf32(bv.y);
        Bs[0][br][bc4 + 2] = wmma::__float_to_tf32(bv.z);
        Bs[0][br][bc4 + 3] = wmma::__float_to_tf32(bv.w);
    }
    __syncthreads();

    for (int kt = 0; kt < ntiles; kt++) {
        int cur = kt & 1, nxt = cur ^ 1;
        bool have = (kt + 1 < ntiles);
        // prefetch next tile into registers
        float4 pa0, pa1, pb;
        if (have) {
            int k0 = (kt + 1) << 4;
            if (arow_ok) {
                pa0 = *(const float4*)(aptr + k0);
                pa1 = *(const float4*)(aptr + k0 + 4);
            } else { pa0 = make_float4(0,0,0,0); pa1 = pa0; }
            pb = *(const float4*)(bptr + (size_t)k0 * Nc);
        }
        // MMA on current buffer
        #pragma unroll
        for (int kk = 0; kk < 16; kk += 8) {
            wmma::fragment<wmma::matrix_a, 16, 16, 8, wmma::precision::tf32, wmma::row_major> af[2];
            wmma::fragment<wmma::matrix_b, 16, 16, 8, wmma::precision::tf32, wmma::row_major> bf[2];
            wmma::load_matrix_sync(af[0], &As[cur][wrow * 32     ][kk], ALD);
            wmma::load_matrix_sync(af[1], &As[cur][wrow * 32 + 16][kk], ALD);
            wmma::load_matrix_sync(bf[0], &Bs[cur][kk][wcol * 32     ], BLD);
            wmma::load_matrix_sync(bf[1], &Bs[cur][kk][wcol * 32 + 16], BLD);
            #pragma unroll
            for (int i = 0; i < 2; i++)
                #pragma unroll
                for (int j = 0; j < 2; j++)
                    wmma::mma_sync(acc[i][j], af[i], bf[j], acc[i][j]);
        }
        // write prefetched tile to the other buffer
        if (have) {
            int k0 = (kt + 1) << 4;
            float av[8] = {pa0.x,pa0.y,pa0.z,pa0.w,pa1.x,pa1.y,pa1.z,pa1.w};
            if (FUSE_BN) {
                #pragma unroll
                for (int j = 0; j < 8; j++) {
                    int c = k0 + ac8 + j;
                    av[j] = bn_elu(av[j], bn_mean[c], bn_rstd[c], bn_g[c], bn_be[c]);
                }
            }
            #pragma unroll
            for (int j = 0; j < 8; j++) As[nxt][ar][ac8 + j] = wmma::__float_to_tf32(av[j]);
            Bs[nxt][br][bc4 + 0] = wmma::__float_to_tf32(pb.x);
            Bs[nxt][br][bc4 + 1] = wmma::__float_to_tf32(pb.y);
            Bs[nxt][br][bc4 + 2] = wmma::__float_to_tf32(pb.z);
            Bs[nxt][br][bc4 + 3] = wmma::__float_to_tf32(pb.w);
        }
        __syncthreads();
    }

    // ---- store C ----
    float* stage = &As[0][0][0] + wid * 256;   // 16x16 per warp
    int lane = tid & 31;
    #pragma unroll
    for (int i = 0; i < 2; i++) {
        int r = row0 + wrow * 32 + i * 16;
        #pragma unroll
        for (int j = 0; j < 2; j++) {
            int c = col0 + wcol * 32 + j * 16;
            if (r + 16 <= M) {
                wmma::store_matrix_sync(C + (size_t)r * Nc + c, acc[i][j], Nc,
                                        wmma::mem_row_major);
            } else if (r < M) {
                wmma::store_matrix_sync(stage, acc[i][j], 16, wmma::mem_row_major);
                __syncwarp();
                for (int t = lane; t < 256; t += 32) {
                    int rr = t >> 4, cc = t & 15;
                    if (r + rr < M)
                        C[(size_t)(r + rr) * Nc + c + cc] = stage[t];
                }
                __syncwarp();
            }
        }
    }

    // ---- fused alpha epilogue (this block's 64 cols == head blockIdx.x) ----
    if (FUSE_ALPHA) {
        __syncthreads();   // make this block's C writes visible block-wide
        if (tid < GBM) {
            int row = row0 + tid;
            if (row < M) {
                int hd = blockIdx.x;
                const float4* cp = (const float4*)(C + (size_t)row * Nc + col0);
                const float4* ap = (const float4*)(a_src + hd * 64);
                const float4* dp = (const float4*)(a_dst + hd * 64);
                float s = 0.f, d = 0.f;
                #pragma unroll
                for (int j = 0; j < 16; j++) {
                    float4 v = cp[j], a = ap[j], b = dp[j];
                    s += v.x*a.x + v.y*a.y + v.z*a.z + v.w*a.w;
                    d += v.x*b.x + v.y*b.y + v.z*b.z + v.w*b.w;
                }
                out_s[(size_t)row * AH + hd] = s;
                out_d[(size_t)row * AH + hd] = d;
            }
        }
    }
}

// -------------------- CSR build (dst-sorted incoming edge lists) ------------
__global__ void degree_kernel(const int* __restrict__ ei, int* __restrict__ deg, int E)
{
    int e = blockIdx.x * blockDim.x + threadIdx.x;
    if (e < E) atomicAdd(&deg[ei[E + e]], 1);
}

__global__ __launch_bounds__(1024) void scan_kernel(
    const int* __restrict__ deg, int* __restrict__ rowptr,
    int* __restrict__ cursor, int N)
{
    __shared__ int part[1024];
    int tid = threadIdx.x;
    int chunk = (N + 1023) / 1024;
    int b = tid * chunk, e = min(b + chunk, N);
    int s = 0;
    for (int i = b; i < e; i++) s += deg[i];
    part[tid] = s;
    __syncthreads();
    for (int o = 1; o < 1024; o <<= 1) {
        int v = (tid >= o) ? part[tid - o] : 0;
        __syncthreads();
        part[tid] += v;
        __syncthreads();
    }
    int run = tid ? part[tid - 1] : 0;
    for (int i = b; i < e; i++) {
        rowptr[i] = run; cursor[i] = run;
        run += deg[i];
    }
    if (tid == 1023) rowptr[N] = part[1023];
}

__global__ void fill_kernel(const int* __restrict__ ei, int* __restrict__ cursor,
                            int* __restrict__ srcs, int E)
{
    int e = blockIdx.x * blockDim.x + threadIdx.x;
    if (e >= E) return;
    int d = ei[E + e];
    int p = atomicAdd(&cursor[d], 1);
    srcs[p] = ei[e];
}

// ---------- layer-1 GAT aggregation: one warp per node, H=4, C=64 ----------
__global__ void gat_agg4_kernel(const int* __restrict__ srcs,
                                const int* __restrict__ rowptr,
                                const float* __restrict__ as_,
                                const float* __restrict__ ad_,
                                const float* __restrict__ h,
                                float* __restrict__ out, int N)
{
    int n = (blockIdx.x * blockDim.x + threadIdx.x) >> 5;
    int lane = threadIdx.x & 31;
    if (n >= N) return;
    int beg = rowptr[n], end = rowptr[n + 1];

    float4 ad4 = *(const float4*)(ad_ + n * 4);
    float4 asS = *(const float4*)(as_ + n * 4);

    float m0 = NEG_BIG, m1 = NEG_BIG, m2 = NEG_BIG, m3 = NEG_BIG;
    float s0 = 0.f, s1 = 0.f, s2 = 0.f, s3 = 0.f;
    if (lane == 0) {    // self loop
        m0 = lrelu(asS.x + ad4.x); s0 = 1.f;
        m1 = lrelu(asS.y + ad4.y); s1 = 1.f;
        m2 = lrelu(asS.z + ad4.z); s2 = 1.f;
        m3 = lrelu(asS.w + ad4.w); s3 = 1.f;
    }
    for (int e = beg + lane; e < end; e += 32) {
        float4 a4 = *(const float4*)(as_ + srcs[e] * 4);
        float v;
        v = lrelu(a4.x + ad4.x);
        if (v > m0) { s0 = s0 * __expf(m0 - v) + 1.f; m0 = v; } else s0 += __expf(v - m0);
        v = lrelu(a4.y + ad4.y);
        if (v > m1) { s1 = s1 * __expf(m1 - v) + 1.f; m1 = v; } else s1 += __expf(v - m1);
        v = lrelu(a4.z + ad4.z);
        if (v > m2) { s2 = s2 * __expf(m2 - v) + 1.f; m2 = v; } else s2 += __expf(v - m2);
        v = lrelu(a4.w + ad4.w);
        if (v > m3) { s3 = s3 * __expf(m3 - v) + 1.f; m3 = v; } else s3 += __expf(v - m3);
    }
    #pragma unroll
    for (int o = 16; o; o >>= 1) {
        float mm, ss, mn;
        mm = __shfl_xor_sync(0xffffffffu, m0, o); ss = __shfl_xor_sync(0xffffffffu, s0, o);
        mn = fmaxf(m0, mm); s0 = s0 * __expf(m0 - mn) + ss * __expf(mm - mn); m0 = mn;
        mm = __shfl_xor_sync(0xffffffffu, m1, o); ss = __shfl_xor_sync(0xffffffffu, s1, o);
        mn = fmaxf(m1, mm); s1 = s1 * __expf(m1 - mn) + ss * __expf(mm - mn); m1 = mn;
        mm = __shfl_xor_sync(0xffffffffu, m2, o); ss = __shfl_xor_sync(0xffffffffu, s2, o);
        mn = fmaxf(m2, mm); s2 = s2 * __expf(m2 - mn) + ss * __expf(mm - mn); m2 = mn;
        mm = __shfl_xor_sync(0xffffffffu, m3, o); ss = __shfl_xor_sync(0xffffffffu, s3, o);
        mn = fmaxf(m3, mm); s3 = s3 * __expf(m3 - mn) + ss * __expf(mm - mn); m3 = mn;
    }

    int hd = lane >> 3;                          // this lane's head
    float mh  = (hd == 0) ? m0 : (hd == 1) ? m1 : (hd == 2) ? m2 : m3;
    float sh  = (hd == 0) ? s0 : (hd == 1) ? s1 : (hd == 2) ? s2 : s3;
    float adh = (hd == 0) ? ad4.x : (hd == 1) ? ad4.y : (hd == 2) ? ad4.z : ad4.w;
    float inv = 1.f / (sh + 1e-16f);

    float4 acc0 = make_float4(0, 0, 0, 0), acc1 = acc0;
    int e = beg;
    for (; e + 2 <= end; e += 2) {      // 2-way unroll for MLP
        int sA = srcs[e], sB = srcs[e + 1];
        float vA = lrelu(as_[sA * 4 + hd] + adh);
        float vB = lrelu(as_[sB * 4 + hd] + adh);
        float aA = __expf(vA - mh) * inv;
        float aB = __expf(vB - mh) * inv;
        const float4* hpA = (const float4*)(h + (size_t)sA * 256 + lane * 8);
        const float4* hpB = (const float4*)(h + (size_t)sB * 256 + lane * 8);
        float4 x0 = hpA[0], x1 = hpA[1], y0 = hpB[0], y1 = hpB[1];
        acc0.x += aA * x0.x + aB * y0.x; acc0.y += aA * x0.y + aB * y0.y;
        acc0.z += aA * x0.z + aB * y0.z; acc0.w += aA * x0.w + aB * y0.w;
        acc1.x += aA * x1.x + aB * y1.x; acc1.y += aA * x1.y + aB * y1.y;
        acc1.z += aA * x1.z + aB * y1.z; acc1.w += aA * x1.w + aB * y1.w;
    }
    for (; e < end; e++) {
        int s = srcs[e];
        float v = lrelu(as_[s * 4 + hd] + adh);
        float a = __expf(v - mh) * inv;
        const float4* hp = (const float4*)(h + (size_t)s * 256 + lane * 8);
        float4 v0 = hp[0], v1 = hp[1];
        acc0.x += a * v0.x; acc0.y += a * v0.y; acc0.z += a * v0.z; acc0.w += a * v0.w;
        acc1.x += a * v1.x; acc1.y += a * v1.y; acc1.z += a * v1.z; acc1.w += a * v1.w;
    }
    {   // self loop
        float v = lrelu(as_[n * 4 + hd] + adh);
        float a = __expf(v - mh) * inv;
        const float4* hp = (const float4*)(h + (size_t)n * 256 + lane * 8);
        float4 v0 = hp[0], v1 = hp[1];
        acc0.x += a * v0.x; acc0.y += a * v0.y; acc0.z += a * v0.z; acc0.w += a * v0.w;
        acc1.x += a * v1.x; acc1.y += a * v1.y; acc1.z += a * v1.z; acc1.w += a * v1.w;
    }
    float4* op = (float4*)(out + (size_t)n * 256 + lane * 8);
    op[0] = acc0; op[1] = acc1;
}

// ---------- layer-2 GAT aggregation: warp per node, H=1, C=64 ---------------
__global__ void gat_agg1_kernel(const int* __restrict__ srcs,
                                const int* __restrict__ rowptr,
                                const float* __restrict__ as_,
                                const float* __restrict__ ad_,
                                const float* __restrict__ h,
                                float* __restrict__ out, int N)
{
    int n = (blockIdx.x * blockDim.x + threadIdx.x) >> 5;
    int lane = threadIdx.x & 31;
    if (n >= N) return;
    int beg = rowptr[n], end = rowptr[n + 1];
    float ad = ad_[n];
    float as_self = as_[n];

    float m = NEG_BIG, ssum = 0.f;
    if (lane == 0) {
        m = lrelu(as_self + ad); ssum = 1.f;
    }
    for (int e = beg + lane; e < end; e += 32) {
        float v = lrelu(as_[srcs[e]] + ad);
        if (v > m) { ssum = ssum * __expf(m - v) + 1.f; m = v; } else ssum += __expf(v - m);
    }
    #pragma unroll
    for (int o = 16; o; o >>= 1) {
        float m2 = __shfl_xor_sync(0xffffffffu, m, o);
        float s2 = __shfl_xor_sync(0xffffffffu, ssum, o);
        float mn = fmaxf(m, m2);
        ssum = ssum * __expf(m - mn) + s2 * __expf(m2 - mn);
        m = mn;
    }
    float inv = 1.f / (ssum + 1e-16f);

    float acc0 = 0.f, acc1 = 0.f;
    int e = beg;
    for (; e + 2 <= end; e += 2) {      // 2-way unroll for MLP
        int sA = srcs[e], sB = srcs[e + 1];
        float aA = __expf(lrelu(as_[sA] + ad) - m) * inv;
        float aB = __expf(lrelu(as_[sB] + ad) - m) * inv;
        const float* hpA = h + (size_t)sA * 64;
        const float* hpB = h + (size_t)sB * 64;
        acc0 += aA * hpA[lane]      + aB * hpB[lane];
        acc1 += aA * hpA[lane + 32] + aB * hpB[lane + 32];
    }
    for (; e < end; e++) {
        int s = srcs[e];
        float a = __expf(lrelu(as_[s] + ad) - m) * inv;
        const float* hp = h + (size_t)s * 64;
        acc0 += a * hp[lane];
        acc1 += a * hp[lane + 32];
    }
    {   // self loop
        float a = __expf(lrelu(as_self + ad) - m) * inv;
        const float* hp = h + (size_t)n * 64;
        acc0 += a * hp[lane];
        acc1 += a * hp[lane + 32];
    }
    float* op = out + (size_t)n * 64;
    op[lane]      = acc0;
    op[lane + 32] = acc1;
}

// -------------------- batchnorm stats (fp32 partials, fp64 combine) ---------
__global__ void bn_stats_kernel(const float* __restrict__ x,
                                double* __restrict__ sum, double* __restrict__ sq,
                                int N, int C)
{
    int c = threadIdx.x;        // blockDim.x == C
    float s = 0.f, q = 0.f;
    for (int r = blockIdx.x; r < N; r += gridDim.x) {
        float v = x[(size_t)r * C + c];
        s += v; q += v * v;
    }
    atomicAdd(&sum[c], (double)s);
    atomicAdd(&sq[c], (double)q);
}

__global__ void bn_final_kernel(const double* __restrict__ sum, const double* __restrict__ sq,
                                float* __restrict__ mean, float* __restrict__ rstd,
                                int N, int C)
{
    int c = blockIdx.x * blockDim.x + threadIdx.x;
    if (c >= C) return;
    double mu = sum[c] / N;
    double var = sq[c] / N - mu * mu;
    mean[c] = (float)mu;
    rstd[c] = (float)(1.0 / sqrt(var + (double)EPS_BN));
}

__global__ void bn_apply_kernel(const float* __restrict__ x, float* __restrict__ y,
                                const float* __restrict__ mean, const float* __restrict__ rstd,
                                const float* __restrict__ g, const float* __restrict__ be,
                                int N, int C, int do_elu)
{
    int i4 = blockIdx.x * blockDim.x + threadIdx.x;      // float4 index
    size_t total4 = ((size_t)N * C) >> 2;
    if ((size_t)i4 >= total4) return;
    int c0 = (i4 << 2) % C;
    float4 v = ((const float4*)x)[i4];
    float r[4] = {v.x, v.y, v.z, v.w};
    #pragma unroll
    for (int j = 0; j < 4; j++) {
        int c = c0 + j;
        float t = (r[j] - mean[c]) * rstd[c] * g[c] + be[c];
        if (do_elu) t = t > 0.f ? t : __expf(t) - 1.f;
        r[j] = t;
    }
    ((float4*)y)[i4] = make_float4(r[0], r[1], r[2], r[3]);
}

// -------------------- launch -----------------------------------------------
extern "C" void kernel_launch(void* const* d_in, const int* in_sizes, int n_in,
                              void* d_out, int out_size)
{
    const float* x   = (const float*)d_in[0];
    const int*   ei  = (const int*)  d_in[1];
    const float* W1  = (const float*)d_in[2];
    const float* a1s = (const float*)d_in[3];
    const float* a1d = (const float*)d_in[4];
    // d_in[5] = b1 : followed by BN -> channel-shift invariant -> skipped
    const float* W2  = (const float*)d_in[6];
    const float* a2s = (const float*)d_in[7];
    const float* a2d = (const float*)d_in[8];
    // d_in[9] = b2 : skipped (BN invariance)
    const float* Wp  = (const float*)d_in[10];
    // d_in[11] = bp : skipped (BN invariance)
    const float* g1  = (const float*)d_in[12];
    const float* be1 = (const float*)d_in[13];
    const float* g2  = (const float*)d_in[14];
    const float* be2 = (const float*)d_in[15];
    const float* g3  = (const float*)d_in[16];
    const float* be3 = (const float*)d_in[17];
    float* out = (float*)d_out;

    const int N = in_sizes[0] / IN_DIM;       // 50000
    const int E = in_sizes[1] / 2;            // 800000

    float *h1, *o1, *as1, *ad1;
    float *h2, *o2, *as2, *ad2, *proj, *meanp, *rstdp, *meanp2, *rstdp2;
    int *deg, *rowptr, *cursor, *srcs;
    double *sump, *sqp, *sump2, *sqp2;
    cudaGetSymbolAddress((void**)&h1,   g_h1);
    cudaGetSymbolAddress((void**)&o1,   g_o1);
    cudaGetSymbolAddress((void**)&as1,  g_as1);
    cudaGetSymbolAddress((void**)&ad1,  g_ad1);
    cudaGetSymbolAddress((void**)&h2,   g_h2);
    cudaGetSymbolAddress((void**)&o2,   g_o2);
    cudaGetSymbolAddress((void**)&as2,  g_as2);
    cudaGetSymbolAddress((void**)&ad2,  g_ad2);
    cudaGetSymbolAddress((void**)&proj, g_proj);
    cudaGetSymbolAddress((void**)&deg,    g_deg);
    cudaGetSymbolAddress((void**)&rowptr, g_rowptr);
    cudaGetSymbolAddress((void**)&cursor, g_cursor);
    cudaGetSymbolAddress((void**)&srcs,   g_srcs);
    cudaGetSymbolAddress((void**)&sump,  g_sum);
    cudaGetSymbolAddress((void**)&sqp,   g_sq);
    cudaGetSymbolAddress((void**)&meanp, g_mean);
    cudaGetSymbolAddress((void**)&rstdp, g_rstd);
    cudaGetSymbolAddress((void**)&sump2,  g_sum2);
    cudaGetSymbolAddress((void**)&sqp2,   g_sq2);
    cudaGetSymbolAddress((void**)&meanp2, g_mean2);
    cudaGetSymbolAddress((void**)&rstdp2, g_rstd2);

    cudaStream_t st = 0;

    // zero stat accumulators up front
    cudaMemsetAsync(sump,  0, D1 * sizeof(double), st);
    cudaMemsetAsync(sqp,   0, D1 * sizeof(double), st);
    cudaMemsetAsync(sump2, 0, D2 * sizeof(double), st);
    cudaMemsetAsync(sqp2,  0, D2 * sizeof(double), st);

    // ---------------- CSR build (shared by both layers) ---------------------
    cudaMemsetAsync(deg, 0, (size_t)N * sizeof(int), st);
    degree_kernel<<<(E + 255) / 256, 256, 0, st>>>(ei, deg, E);
    scan_kernel<<<1, 1024, 0, st>>>(deg, rowptr, cursor, N);
    fill_kernel<<<(E + 255) / 256, 256, 0, st>>>(ei, cursor, srcs, E);

    // ---------------- layer 1: GATConv(128 -> 4x64, concat) ----------------
    // alpha fused into GEMM epilogue (each column block == one head)
    {
        dim3 grid(D1 / GBN, (N + GBM - 1) / GBM);
        gemm_tf32_kernel<false, true><<<grid, 256, 0, st>>>(
            x, W1, h1, N, D1, IN_DIM,
            nullptr, nullptr, nullptr, nullptr,
            a1s, a1d, as1, ad1, H1N);
    }
    gat_agg4_kernel<<<(N * 32 + 255) / 256, 256, 0, st>>>(
        srcs, rowptr, as1, ad1, h1, o1, N);

    // BN1 stats on o1 (apply fused into gemm2's A load)
    bn_stats_kernel<<<512, D1, 0, st>>>(o1, sump, sqp, N, D1);
    bn_final_kernel<<<1, D1, 0, st>>>(sump, sqp, meanp, rstdp, N, D1);

    // ---------------- layer 2: GATConv(256 -> 64, H=1) ---------------------
    // BN1+ELU fused into A-tile load; alpha2 fused into epilogue.
    {
        dim3 grid(D2 / GBN, (N + GBM - 1) / GBM);
        gemm_tf32_kernel<true, true><<<grid, 256, 0, st>>>(
            o1, W2, h2, N, D2, D1,
            meanp, rstdp, g1, be1,
            a2s, a2d, as2, ad2, 1);
    }
    gat_agg1_kernel<<<(N * 32 + 255) / 256, 256, 0, st>>>(
        srcs, rowptr, as2, ad2, h2, o2, N);

    // BN2 stats on o2 (apply fused into gemm3's A load)
    bn_stats_kernel<<<512, D2, 0, st>>>(o2, sump2, sqp2, N, D2);
    bn_final_kernel<<<1, D2, 0, st>>>(sump2, sqp2, meanp2, rstdp2, N, D2);

    // ---------------- projection 64 -> 128 + BN3 ---------------------------
    // BN2+ELU fused into the A-tile load (A = o2).
    {
        dim3 grid(IN_DIM / GBN, (N + GBM - 1) / GBM);
        gemm_tf32_kernel<true, false><<<grid, 256, 0, st>>>(
            o2, Wp, proj, N, IN_DIM, D2,
            meanp2, rstdp2, g2, be2,
            nullptr, nullptr, nullptr, nullptr, 1);
    }
    cudaMemsetAsync(sump, 0, IN_DIM * sizeof(double), st);
    cudaMemsetAsync(sqp,  0, IN_DIM * sizeof(double), st);
    bn_stats_kernel<<<512, IN_DIM, 0, st>>>(proj, sump, sqp, N, IN_DIM);
    bn_final_kernel<<<1, IN_DIM, 0, st>>>(sump, sqp, meanp, rstdp, N, IN_DIM);
    bn_apply_kernel<<<(((size_t)N * IN_DIM / 4) + 255) / 256, 256, 0, st>>>(
        proj, out, meanp, rstdp, g3, be3, N, IN_DIM, 0);
}

// round 13
// speedup vs baseline: 1.6491x; 1.0451x over previous
#include <cuda_runtime.h>
#include <cuda_bf16.h>
#include <mma.h>
#include <math.h>

using namespace nvcuda;

// Problem constants (shapes fixed by the dataset).
#define NN      50000
#define EEDGES  800000
#define IN_DIM  128
#define H1N     4
#define C1N     64
#define D1      (H1N * C1N)          // 256
#define D2      64
#define EPS_BN  1e-5f
#define NEG_SLOPE 0.2f
#define NEG_BIG  (-1e30f)

// -------------------- scratch (static __device__, no allocs) ----------------
__device__ float    g_h1  [NN * D1];
__device__ float    g_o1  [NN * D1];
__device__ float    g_as1 [NN * H1N];
__device__ float    g_ad1 [NN * H1N];
__device__ float    g_h2  [NN * D2];
__device__ float    g_o2  [NN * D2];
__device__ float    g_as2 [NN];
__device__ float    g_ad2 [NN];
__device__ float    g_proj[NN * IN_DIM];
__device__ int      g_deg [NN];
__device__ int      g_rowptr[NN + 1];
__device__ int      g_cursor[NN];
__device__ int      g_srcs[EEDGES];
__device__ double   g_sum [256];
__device__ double   g_sq  [256];
__device__ float    g_mean[256];
__device__ float    g_rstd[256];
__device__ double   g_sum2[64];
__device__ double   g_sq2 [64];
__device__ float    g_mean2[64];
__device__ float    g_rstd2[64];

__device__ __forceinline__ float lrelu(float v) {
    return v > 0.f ? v : NEG_SLOPE * v;
}
__device__ __forceinline__ float bn_elu(float v, float mu, float rs, float ga, float bb) {
    float t = (v - mu) * rs * ga + bb;
    return t > 0.f ? t : __expf(t) - 1.f;
}

// ------------- GEMM (TF32 tensor cores): C[M,Nc] = A[M,K] @ B[K,Nc] ---------
// BM=128, BN=64, BK=16. 256 threads = 8 warps in 4x2; each warp 32x32 output
// via 2x2 wmma m16n16k8 accumulators. SINGLE-buffered smem (proven config:
// 64 regs, occ ~45%, tensor ~33% — double-buffering regressed to occ 22%).
// FUSE_BN:    apply per-K-channel BN+ELU to A while staging.
// FUSE_ALPHA: block's 64 columns == one head; epilogue computes
//             as/ad[row*AH + blockIdx.x] = dot(C_row_segment, a_src/a_dst).
#define GBM 128
#define GBN 64
#define ALD 20      // A smem leading dim (mult of 4)
#define BLD 68      // B smem leading dim (mult of 4)
template<bool FUSE_BN, bool FUSE_ALPHA>
__global__ __launch_bounds__(256) void gemm_tf32_kernel(
    const float* __restrict__ A, const float* __restrict__ B,
    float* __restrict__ C, int M, int Nc, int K,
    const float* __restrict__ bn_mean, const float* __restrict__ bn_rstd,
    const float* __restrict__ bn_g,    const float* __restrict__ bn_be,
    const float* __restrict__ a_src,   const float* __restrict__ a_dst,
    float* __restrict__ out_s, float* __restrict__ out_d, int AH)
{
    __shared__ float As[GBM][ALD];   // 128x16 tile (tf32 values)
    __shared__ float Bs[16][BLD];    // 16x64 tile
    int tid = threadIdx.x;
    int wid  = tid >> 5;
    int wrow = wid >> 1;             // 0..3 -> 32-row strip
    int wcol = wid & 1;              // 0..1 -> 32-col strip
    int row0 = blockIdx.y * GBM, col0 = blockIdx.x * GBN;

    wmma::fragment<wmma::accumulator, 16, 16, 8, float> acc[2][2];
    #pragma unroll
    for (int i = 0; i < 2; i++)
        #pragma unroll
        for (int j = 0; j < 2; j++) wmma::fill_fragment(acc[i][j], 0.f);

    for (int k0 = 0; k0 < K; k0 += 16) {
        {   // A tile: 128 rows x 16 k. Each thread: one row, 8 k (2 float4).
            int r  = tid >> 1;
            int c8 = (tid & 1) * 8;
            float4 v0 = make_float4(0, 0, 0, 0), v1 = v0;
            if (row0 + r < M) {
                const float* ap = A + (size_t)(row0 + r) * K + k0 + c8;
                v0 = *(const float4*)ap;
                v1 = *(const float4*)(ap + 4);
            }
            float av[8] = {v0.x, v0.y, v0.z, v0.w, v1.x, v1.y, v1.z, v1.w};
            if (FUSE_BN) {
                #pragma unroll
                for (int j = 0; j < 8; j++) {
                    int c = k0 + c8 + j;
                    av[j] = bn_elu(av[j], bn_mean[c], bn_rstd[c], bn_g[c], bn_be[c]);
                }
            }
            #pragma unroll
            for (int j = 0; j < 8; j++)
                As[r][c8 + j] = wmma::__float_to_tf32(av[j]);
        }
        {   // B tile: 16 k x 64 cols. Each thread one float4.
            int r  = tid >> 4;
            int c4 = (tid & 15) * 4;
            float4 v = *(const float4*)(B + (size_t)(k0 + r) * Nc + col0 + c4);
            Bs[r][c4 + 0] = wmma::__float_to_tf32(v.x);
            Bs[r][c4 + 1] = wmma::__float_to_tf32(v.y);
            Bs[r][c4 + 2] = wmma::__float_to_tf32(v.z);
            Bs[r][c4 + 3] = wmma::__float_to_tf32(v.w);
        }
        __syncthreads();
        #pragma unroll
        for (int kk = 0; kk < 16; kk += 8) {
            wmma::fragment<wmma::matrix_a, 16, 16, 8, wmma::precision::tf32, wmma::row_major> af[2];
            wmma::fragment<wmma::matrix_b, 16, 16, 8, wmma::precision::tf32, wmma::row_major> bf[2];
            wmma::load_matrix_sync(af[0], &As[wrow * 32     ][kk], ALD);
            wmma::load_matrix_sync(af[1], &As[wrow * 32 + 16][kk], ALD);
            wmma::load_matrix_sync(bf[0], &Bs[kk][wcol * 32     ], BLD);
            wmma::load_matrix_sync(bf[1], &Bs[kk][wcol * 32 + 16], BLD);
            #pragma unroll
            for (int i = 0; i < 2; i++)
                #pragma unroll
                for (int j = 0; j < 2; j++)
                    wmma::mma_sync(acc[i][j], af[i], bf[j], acc[i][j]);
        }
        __syncthreads();
    }

    // ---- store C (M may not be mult of 16: stage partial tiles) ----
    float* stage = &As[0][0] + wid * 256;   // 16x16 per warp
    int lane = tid & 31;
    #pragma unroll
    for (int i = 0; i < 2; i++) {
        int r = row0 + wrow * 32 + i * 16;
        #pragma unroll
        for (int j = 0; j < 2; j++) {
            int c = col0 + wcol * 32 + j * 16;
            if (r + 16 <= M) {
                wmma::store_matrix_sync(C + (size_t)r * Nc + c, acc[i][j], Nc,
                                        wmma::mem_row_major);
            } else if (r < M) {
                wmma::store_matrix_sync(stage, acc[i][j], 16, wmma::mem_row_major);
                __syncwarp();
                for (int t = lane; t < 256; t += 32) {
                    int rr = t >> 4, cc = t & 15;
                    if (r + rr < M)
                        C[(size_t)(r + rr) * Nc + c + cc] = stage[t];
                }
                __syncwarp();
            }
        }
    }

    // ---- fused alpha epilogue (this block's 64 cols == head blockIdx.x) ----
    if (FUSE_ALPHA) {
        __syncthreads();   // make this block's C writes visible block-wide
        if (tid < GBM) {
            int row = row0 + tid;
            if (row < M) {
                int hd = blockIdx.x;
                const float4* cp = (const float4*)(C + (size_t)row * Nc + col0);
                const float4* ap = (const float4*)(a_src + hd * 64);
                const float4* dp = (const float4*)(a_dst + hd * 64);
                float s = 0.f, d = 0.f;
                #pragma unroll
                for (int j = 0; j < 16; j++) {
                    float4 v = cp[j], a = ap[j], b = dp[j];
                    s += v.x*a.x + v.y*a.y + v.z*a.z + v.w*a.w;
                    d += v.x*b.x + v.y*b.y + v.z*b.z + v.w*b.w;
                }
                out_s[(size_t)row * AH + hd] = s;
                out_d[(size_t)row * AH + hd] = d;
            }
        }
    }
}

// -------------------- CSR build (dst-sorted incoming edge lists) ------------
__global__ void degree_kernel(const int* __restrict__ ei, int* __restrict__ deg, int E)
{
    int e = blockIdx.x * blockDim.x + threadIdx.x;
    if (e < E) atomicAdd(&deg[ei[E + e]], 1);
}

__global__ __launch_bounds__(1024) void scan_kernel(
    const int* __restrict__ deg, int* __restrict__ rowptr,
    int* __restrict__ cursor, int N)
{
    __shared__ int part[1024];
    int tid = threadIdx.x;
    int chunk = (N + 1023) / 1024;
    int b = tid * chunk, e = min(b + chunk, N);
    int s = 0;
    for (int i = b; i < e; i++) s += deg[i];
    part[tid] = s;
    __syncthreads();
    for (int o = 1; o < 1024; o <<= 1) {
        int v = (tid >= o) ? part[tid - o] : 0;
        __syncthreads();
        part[tid] += v;
        __syncthreads();
    }
    int run = tid ? part[tid - 1] : 0;
    for (int i = b; i < e; i++) {
        rowptr[i] = run; cursor[i] = run;
        run += deg[i];
    }
    if (tid == 1023) rowptr[N] = part[1023];
}

__global__ void fill_kernel(const int* __restrict__ ei, int* __restrict__ cursor,
                            int* __restrict__ srcs, int E)
{
    int e = blockIdx.x * blockDim.x + threadIdx.x;
    if (e >= E) return;
    int d = ei[E + e];
    int p = atomicAdd(&cursor[d], 1);
    srcs[p] = ei[e];
}

// ---------- layer-1 GAT aggregation: one warp per node, H=4, C=64 ----------
__global__ void gat_agg4_kernel(const int* __restrict__ srcs,
                                const int* __restrict__ rowptr,
                                const float* __restrict__ as_,
                                const float* __restrict__ ad_,
                                const float* __restrict__ h,
                                float* __restrict__ out, int N)
{
    int n = (blockIdx.x * blockDim.x + threadIdx.x) >> 5;
    int lane = threadIdx.x & 31;
    if (n >= N) return;
    int beg = rowptr[n], end = rowptr[n + 1];

    float4 ad4 = *(const float4*)(ad_ + n * 4);
    float4 asS = *(const float4*)(as_ + n * 4);

    float m0 = NEG_BIG, m1 = NEG_BIG, m2 = NEG_BIG, m3 = NEG_BIG;
    float s0 = 0.f, s1 = 0.f, s2 = 0.f, s3 = 0.f;
    if (lane == 0) {    // self loop
        m0 = lrelu(asS.x + ad4.x); s0 = 1.f;
        m1 = lrelu(asS.y + ad4.y); s1 = 1.f;
        m2 = lrelu(asS.z + ad4.z); s2 = 1.f;
        m3 = lrelu(asS.w + ad4.w); s3 = 1.f;
    }
    for (int e = beg + lane; e < end; e += 32) {
        float4 a4 = *(const float4*)(as_ + srcs[e] * 4);
        float v;
        v = lrelu(a4.x + ad4.x);
        if (v > m0) { s0 = s0 * __expf(m0 - v) + 1.f; m0 = v; } else s0 += __expf(v - m0);
        v = lrelu(a4.y + ad4.y);
        if (v > m1) { s1 = s1 * __expf(m1 - v) + 1.f; m1 = v; } else s1 += __expf(v - m1);
        v = lrelu(a4.z + ad4.z);
        if (v > m2) { s2 = s2 * __expf(m2 - v) + 1.f; m2 = v; } else s2 += __expf(v - m2);
        v = lrelu(a4.w + ad4.w);
        if (v > m3) { s3 = s3 * __expf(m3 - v) + 1.f; m3 = v; } else s3 += __expf(v - m3);
    }
    #pragma unroll
    for (int o = 16; o; o >>= 1) {
        float mm, ss, mn;
        mm = __shfl_xor_sync(0xffffffffu, m0, o); ss = __shfl_xor_sync(0xffffffffu, s0, o);
        mn = fmaxf(m0, mm); s0 = s0 * __expf(m0 - mn) + ss * __expf(mm - mn); m0 = mn;
        mm = __shfl_xor_sync(0xffffffffu, m1, o); ss = __shfl_xor_sync(0xffffffffu, s1, o);
        mn = fmaxf(m1, mm); s1 = s1 * __expf(m1 - mn) + ss * __expf(mm - mn); m1 = mn;
        mm = __shfl_xor_sync(0xffffffffu, m2, o); ss = __shfl_xor_sync(0xffffffffu, s2, o);
        mn = fmaxf(m2, mm); s2 = s2 * __expf(m2 - mn) + ss * __expf(mm - mn); m2 = mn;
        mm = __shfl_xor_sync(0xffffffffu, m3, o); ss = __shfl_xor_sync(0xffffffffu, s3, o);
        mn = fmaxf(m3, mm); s3 = s3 * __expf(m3 - mn) + ss * __expf(mm - mn); m3 = mn;
    }

    int hd = lane >> 3;                          // this lane's head
    float mh  = (hd == 0) ? m0 : (hd == 1) ? m1 : (hd == 2) ? m2 : m3;
    float sh  = (hd == 0) ? s0 : (hd == 1) ? s1 : (hd == 2) ? s2 : s3;
    float adh = (hd == 0) ? ad4.x : (hd == 1) ? ad4.y : (hd == 2) ? ad4.z : ad4.w;
    float inv = 1.f / (sh + 1e-16f);

    float4 acc0 = make_float4(0, 0, 0, 0), acc1 = acc0;
    int e = beg;
    for (; e + 2 <= end; e += 2) {      // 2-way unroll for MLP
        int sA = srcs[e], sB = srcs[e + 1];
        float vA = lrelu(as_[sA * 4 + hd] + adh);
        float vB = lrelu(as_[sB * 4 + hd] + adh);
        float aA = __expf(vA - mh) * inv;
        float aB = __expf(vB - mh) * inv;
        const float4* hpA = (const float4*)(h + (size_t)sA * 256 + lane * 8);
        const float4* hpB = (const float4*)(h + (size_t)sB * 256 + lane * 8);
        float4 x0 = hpA[0], x1 = hpA[1], y0 = hpB[0], y1 = hpB[1];
        acc0.x += aA * x0.x + aB * y0.x; acc0.y += aA * x0.y + aB * y0.y;
        acc0.z += aA * x0.z + aB * y0.z; acc0.w += aA * x0.w + aB * y0.w;
        acc1.x += aA * x1.x + aB * y1.x; acc1.y += aA * x1.y + aB * y1.y;
        acc1.z += aA * x1.z + aB * y1.z; acc1.w += aA * x1.w + aB * y1.w;
    }
    for (; e < end; e++) {
        int s = srcs[e];
        float v = lrelu(as_[s * 4 + hd] + adh);
        float a = __expf(v - mh) * inv;
        const float4* hp = (const float4*)(h + (size_t)s * 256 + lane * 8);
        float4 v0 = hp[0], v1 = hp[1];
        acc0.x += a * v0.x; acc0.y += a * v0.y; acc0.z += a * v0.z; acc0.w += a * v0.w;
        acc1.x += a * v1.x; acc1.y += a * v1.y; acc1.z += a * v1.z; acc1.w += a * v1.w;
    }
    {   // self loop
        float v = lrelu(as_[n * 4 + hd] + adh);
        float a = __expf(v - mh) * inv;
        const float4* hp = (const float4*)(h + (size_t)n * 256 + lane * 8);
        float4 v0 = hp[0], v1 = hp[1];
        acc0.x += a * v0.x; acc0.y += a * v0.y; acc0.z += a * v0.z; acc0.w += a * v0.w;
        acc1.x += a * v1.x; acc1.y += a * v1.y; acc1.z += a * v1.z; acc1.w += a * v1.w;
    }
    float4* op = (float4*)(out + (size_t)n * 256 + lane * 8);
    op[0] = acc0; op[1] = acc1;
}

// ---------- layer-2 GAT aggregation: warp per node, H=1, C=64 ---------------
__global__ void gat_agg1_kernel(const int* __restrict__ srcs,
                                const int* __restrict__ rowptr,
                                const float* __restrict__ as_,
                                const float* __restrict__ ad_,
                                const float* __restrict__ h,
                                float* __restrict__ out, int N)
{
    int n = (blockIdx.x * blockDim.x + threadIdx.x) >> 5;
    int lane = threadIdx.x & 31;
    if (n >= N) return;
    int beg = rowptr[n], end = rowptr[n + 1];
    float ad = ad_[n];
    float as_self = as_[n];

    float m = NEG_BIG, ssum = 0.f;
    if (lane == 0) {
        m = lrelu(as_self + ad); ssum = 1.f;
    }
    for (int e = beg + lane; e < end; e += 32) {
        float v = lrelu(as_[srcs[e]] + ad);
        if (v > m) { ssum = ssum * __expf(m - v) + 1.f; m = v; } else ssum += __expf(v - m);
    }
    #pragma unroll
    for (int o = 16; o; o >>= 1) {
        float m2 = __shfl_xor_sync(0xffffffffu, m, o);
        float s2 = __shfl_xor_sync(0xffffffffu, ssum, o);
        float mn = fmaxf(m, m2);
        ssum = ssum * __expf(m - mn) + s2 * __expf(m2 - mn);
        m = mn;
    }
    float inv = 1.f / (ssum + 1e-16f);

    float acc0 = 0.f, acc1 = 0.f;
    int e = beg;
    for (; e + 2 <= end; e += 2) {      // 2-way unroll for MLP
        int sA = srcs[e], sB = srcs[e + 1];
        float aA = __expf(lrelu(as_[sA] + ad) - m) * inv;
        float aB = __expf(lrelu(as_[sB] + ad) - m) * inv;
        const float* hpA = h + (size_t)sA * 64;
        const float* hpB = h + (size_t)sB * 64;
        acc0 += aA * hpA[lane]      + aB * hpB[lane];
        acc1 += aA * hpA[lane + 32] + aB * hpB[lane + 32];
    }
    for (; e < end; e++) {
        int s = srcs[e];
        float a = __expf(lrelu(as_[s] + ad) - m) * inv;
        const float* hp = h + (size_t)s * 64;
        acc0 += a * hp[lane];
        acc1 += a * hp[lane + 32];
    }
    {   // self loop
        float a = __expf(lrelu(as_self + ad) - m) * inv;
        const float* hp = h + (size_t)n * 64;
        acc0 += a * hp[lane];
        acc1 += a * hp[lane + 32];
    }
    float* op = out + (size_t)n * 64;
    op[lane]      = acc0;
    op[lane + 32] = acc1;
}

// -------------------- batchnorm stats (fp32 partials, fp64 combine) ---------
__global__ void bn_stats_kernel(const float* __restrict__ x,
                                double* __restrict__ sum, double* __restrict__ sq,
                                int N, int C)
{
    int c = threadIdx.x;        // blockDim.x == C
    float s = 0.f, q = 0.f;
    for (int r = blockIdx.x; r < N; r += gridDim.x) {
        float v = x[(size_t)r * C + c];
        s += v; q += v * v;
    }
    atomicAdd(&sum[c], (double)s);
    atomicAdd(&sq[c], (double)q);
}

__global__ void bn_final_kernel(const double* __restrict__ sum, const double* __restrict__ sq,
                                float* __restrict__ mean, float* __restrict__ rstd,
                                int N, int C)
{
    int c = blockIdx.x * blockDim.x + threadIdx.x;
    if (c >= C) return;
    double mu = sum[c] / N;
    double var = sq[c] / N - mu * mu;
    mean[c] = (float)mu;
    rstd[c] = (float)(1.0 / sqrt(var + (double)EPS_BN));
}

__global__ void bn_apply_kernel(const float* __restrict__ x, float* __restrict__ y,
                                const float* __restrict__ mean, const float* __restrict__ rstd,
                                const float* __restrict__ g, const float* __restrict__ be,
                                int N, int C, int do_elu)
{
    int i4 = blockIdx.x * blockDim.x + threadIdx.x;      // float4 index
    size_t total4 = ((size_t)N * C) >> 2;
    if ((size_t)i4 >= total4) return;
    int c0 = (i4 << 2) % C;
    float4 v = ((const float4*)x)[i4];
    float r[4] = {v.x, v.y, v.z, v.w};
    #pragma unroll
    for (int j = 0; j < 4; j++) {
        int c = c0 + j;
        float t = (r[j] - mean[c]) * rstd[c] * g[c] + be[c];
        if (do_elu) t = t > 0.f ? t : __expf(t) - 1.f;
        r[j] = t;
    }
    ((float4*)y)[i4] = make_float4(r[0], r[1], r[2], r[3]);
}

// -------------------- launch -----------------------------------------------
extern "C" void kernel_launch(void* const* d_in, const int* in_sizes, int n_in,
                              void* d_out, int out_size)
{
    const float* x   = (const float*)d_in[0];
    const int*   ei  = (const int*)  d_in[1];
    const float* W1  = (const float*)d_in[2];
    const float* a1s = (const float*)d_in[3];
    const float* a1d = (const float*)d_in[4];
    // d_in[5] = b1 : followed by BN -> channel-shift invariant -> skipped
    const float* W2  = (const float*)d_in[6];
    const float* a2s = (const float*)d_in[7];
    const float* a2d = (const float*)d_in[8];
    // d_in[9] = b2 : skipped (BN invariance)
    const float* Wp  = (const float*)d_in[10];
    // d_in[11] = bp : skipped (BN invariance)
    const float* g1  = (const float*)d_in[12];
    const float* be1 = (const float*)d_in[13];
    const float* g2  = (const float*)d_in[14];
    const float* be2 = (const float*)d_in[15];
    const float* g3  = (const float*)d_in[16];
    const float* be3 = (const float*)d_in[17];
    float* out = (float*)d_out;

    const int N = in_sizes[0] / IN_DIM;       // 50000
    const int E = in_sizes[1] / 2;            // 800000

    float *h1, *o1, *as1, *ad1;
    float *h2, *o2, *as2, *ad2, *proj, *meanp, *rstdp, *meanp2, *rstdp2;
    int *deg, *rowptr, *cursor, *srcs;
    double *sump, *sqp, *sump2, *sqp2;
    cudaGetSymbolAddress((void**)&h1,   g_h1);
    cudaGetSymbolAddress((void**)&o1,   g_o1);
    cudaGetSymbolAddress((void**)&as1,  g_as1);
    cudaGetSymbolAddress((void**)&ad1,  g_ad1);
    cudaGetSymbolAddress((void**)&h2,   g_h2);
    cudaGetSymbolAddress((void**)&o2,   g_o2);
    cudaGetSymbolAddress((void**)&as2,  g_as2);
    cudaGetSymbolAddress((void**)&ad2,  g_ad2);
    cudaGetSymbolAddress((void**)&proj, g_proj);
    cudaGetSymbolAddress((void**)&deg,    g_deg);
    cudaGetSymbolAddress((void**)&rowptr, g_rowptr);
    cudaGetSymbolAddress((void**)&cursor, g_cursor);
    cudaGetSymbolAddress((void**)&srcs,   g_srcs);
    cudaGetSymbolAddress((void**)&sump,  g_sum);
    cudaGetSymbolAddress((void**)&sqp,   g_sq);
    cudaGetSymbolAddress((void**)&meanp, g_mean);
    cudaGetSymbolAddress((void**)&rstdp, g_rstd);
    cudaGetSymbolAddress((void**)&sump2,  g_sum2);
    cudaGetSymbolAddress((void**)&sqp2,   g_sq2);
    cudaGetSymbolAddress((void**)&meanp2, g_mean2);
    cudaGetSymbolAddress((void**)&rstdp2, g_rstd2);

    cudaStream_t st = 0;

    // zero stat accumulators up front
    cudaMemsetAsync(sump,  0, D1 * sizeof(double), st);
    cudaMemsetAsync(sqp,   0, D1 * sizeof(double), st);
    cudaMemsetAsync(sump2, 0, D2 * sizeof(double), st);
    cudaMemsetAsync(sqp2,  0, D2 * sizeof(double), st);

    // ---------------- CSR build (shared by both layers) ---------------------
    cudaMemsetAsync(deg, 0, (size_t)N * sizeof(int), st);
    degree_kernel<<<(E + 255) / 256, 256, 0, st>>>(ei, deg, E);
    scan_kernel<<<1, 1024, 0, st>>>(deg, rowptr, cursor, N);
    fill_kernel<<<(E + 255) / 256, 256, 0, st>>>(ei, cursor, srcs, E);

    // ---------------- layer 1: GATConv(128 -> 4x64, concat) ----------------
    // alpha fused into GEMM epilogue (each column block == one head)
    {
        dim3 grid(D1 / GBN, (N + GBM - 1) / GBM);
        gemm_tf32_kernel<false, true><<<grid, 256, 0, st>>>(
            x, W1, h1, N, D1, IN_DIM,
            nullptr, nullptr, nullptr, nullptr,
            a1s, a1d, as1, ad1, H1N);
    }
    gat_agg4_kernel<<<(N * 32 + 255) / 256, 256, 0, st>>>(
        srcs, rowptr, as1, ad1, h1, o1, N);

    // BN1 stats on o1 (apply fused into gemm2's A load)
    bn_stats_kernel<<<512, D1, 0, st>>>(o1, sump, sqp, N, D1);
    bn_final_kernel<<<1, D1, 0, st>>>(sump, sqp, meanp, rstdp, N, D1);

    // ---------------- layer 2: GATConv(256 -> 64, H=1) ---------------------
    // BN1+ELU fused into A-tile load; alpha2 fused into epilogue.
    {
        dim3 grid(D2 / GBN, (N + GBM - 1) / GBM);
        gemm_tf32_kernel<true, true><<<grid, 256, 0, st>>>(
            o1, W2, h2, N, D2, D1,
            meanp, rstdp, g1, be1,
            a2s, a2d, as2, ad2, 1);
    }
    gat_agg1_kernel<<<(N * 32 + 255) / 256, 256, 0, st>>>(
        srcs, rowptr, as2, ad2, h2, o2, N);

    // BN2 stats on o2 (apply fused into gemm3's A load)
    bn_stats_kernel<<<512, D2, 0, st>>>(o2, sump2, sqp2, N, D2);
    bn_final_kernel<<<1, D2, 0, st>>>(sump2, sqp2, meanp2, rstdp2, N, D2);

    // ---------------- projection 64 -> 128 + BN3 ---------------------------
    // BN2+ELU fused into the A-tile load (A = o2).
    {
        dim3 grid(IN_DIM / GBN, (N + GBM - 1) / GBM);
        gemm_tf32_kernel<true, false><<<grid, 256, 0, st>>>(
            o2, Wp, proj, N, IN_DIM, D2,
            meanp2, rstdp2, g2, be2,
            nullptr, nullptr, nullptr, nullptr, 1);
    }
    cudaMemsetAsync(sump, 0, IN_DIM * sizeof(double), st);
    cudaMemsetAsync(sqp,  0, IN_DIM * sizeof(double), st);
    bn_stats_kernel<<<512, IN_DIM, 0, st>>>(proj, sump, sqp, N, IN_DIM);
    bn_final_kernel<<<1, IN_DIM, 0, st>>>(sump, sqp, meanp, rstdp, N, IN_DIM);
    bn_apply_kernel<<<(((size_t)N * IN_DIM / 4) + 255) / 256, 256, 0, st>>>(
        proj, out, meanp, rstdp, g3, be3, N, IN_DIM, 0);
}